// round 1
// baseline (speedup 1.0000x reference)
#include <cuda_runtime.h>
#include <math.h>

#define NN   199
#define NP   200            // padded row stride (16B-aligned float4 rows)
#define FF   64
#define UU   64
#define HH   4
#define OUTC (HH*UU + NN)   // 455

// Precomputed transposed masked adjacency weights: AWT[h][m][n] = A[n][m]*params[h][n][m]
__device__ float g_AWT[HH * NN * NP];

__global__ void awt_kernel(const float* __restrict__ A, const float* __restrict__ params) {
    int idx = blockIdx.x * blockDim.x + threadIdx.x;
    const int total = HH * NN * NP;
    if (idx >= total) return;
    int n = idx % NP;
    int m = (idx / NP) % NN;
    int h = idx / (NP * NN);
    float v = 0.f;
    if (n < NN) v = A[n * NN + m] * params[((size_t)h * NN + n) * NN + m];
    g_AWT[idx] = v;
}

__global__ __launch_bounds__(512, 1)
void gc_kernel(const float* __restrict__ X, const float* __restrict__ A,
               const float* __restrict__ kernels, const float* __restrict__ fc,
               const float* __restrict__ bias1, const float* __restrict__ bias2,
               float* __restrict__ out)
{
    extern __shared__ float sm[];
    float* Xs   = sm;                       // [NP][FF] (row NN zeroed)
    float* Ks   = Xs + NP * FF;             // [FF][NP] (col NN zeroed)
    float* fcs  = Ks + FF * NP;             // [FF][UU]
    float* frow = fcs + FF * UU;            // [16][FF]
    float* nrow = frow + 16 * FF;           // [16][FF]
    float* mrow = nrow + 16 * FF;           // [16][NP]
    float* b1s  = mrow + 16 * NP;           // [NP]
    float* b2s  = b1s + NP;                 // [UU]

    const int bx   = blockIdx.x;
    const int h    = bx % HH;
    const int b    = bx / HH;
    const int tid  = threadIdx.x;
    const int lane = tid & 31;
    const int w    = tid >> 5;

    // ---------------- cooperative staging ----------------
    {
        const float4* Xg4 = (const float4*)(X + (size_t)b * NN * FF);
        float4* Xs4 = (float4*)Xs;
        #pragma unroll 1
        for (int i = tid; i < NN * FF / 4; i += 512) Xs4[i] = Xg4[i];
        for (int i = tid; i < FF; i += 512) Xs[NN * FF + i] = 0.f;   // zero pad row

        const float* Kg = kernels + (size_t)h * FF * NN;
        #pragma unroll 1
        for (int i = tid; i < FF * NP; i += 512) {
            int f = i / NP, j = i - f * NP;
            Ks[i] = (j < NN) ? Kg[f * NN + j] : 0.f;
        }
        const float4* fg4 = (const float4*)(fc + (size_t)h * FF * UU);
        float4* fcs4 = (float4*)fcs;
        for (int i = tid; i < FF * UU / 4; i += 512) fcs4[i] = fg4[i];

        for (int i = tid; i < NP; i += 512) b1s[i] = (i < NN) ? bias1[h * NN + i] : 0.f;
        for (int i = tid; i < UU; i += 512) b2s[i] = bias2[h * UU + i];
        if (lane == 0) mrow[w * NP + NN] = 0.f;   // pad of per-warp mask row stays 0
    }
    __syncthreads();

    const int f0 = 2 * lane;
    float* fr = frow + w * FF;
    float* nr = nrow + w * FF;
    float* mr = mrow + w * NP;

    for (int m = w; m < NN; m += 16) {
        // ---------- phase 1: feat row  feat[f] = sum_n AWT[m][n] * X[n][f] ----------
        const float4* aw4 = (const float4*)(g_AWT + ((size_t)h * NN + m) * NP);
        float2 fa = make_float2(0.f, 0.f);
        #pragma unroll 5
        for (int c = 0; c < NP / 4; c++) {
            float4 a = __ldg(&aw4[c]);
            int n = c * 4;
            float2 x;
            x = *(const float2*)&Xs[(n + 0) * FF + f0]; fa.x += a.x * x.x; fa.y += a.x * x.y;
            x = *(const float2*)&Xs[(n + 1) * FF + f0]; fa.x += a.y * x.x; fa.y += a.y * x.y;
            x = *(const float2*)&Xs[(n + 2) * FF + f0]; fa.x += a.z * x.x; fa.y += a.z * x.y;
            x = *(const float2*)&Xs[(n + 3) * FF + f0]; fa.x += a.w * x.x; fa.y += a.w * x.y;
        }
        fr[f0] = fa.x; fr[f0 + 1] = fa.y;
        __syncwarp();

        // ---------- phase 2: dense row  dense[j] = sum_f feat[f]*K[f][j] ----------
        // lane owns 8 j-slots: j = 64*k + f0 + i,  k in 0..3, i in 0..1
        float2 d0 = {0,0}, d1 = {0,0}, d2 = {0,0}, d3 = {0,0};
        #pragma unroll 4
        for (int fb = 0; fb < FF; fb += 4) {
            float4 fv = *(const float4*)&fr[fb];
            #pragma unroll
            for (int i = 0; i < 4; i++) {
                float fvi = (i == 0) ? fv.x : (i == 1) ? fv.y : (i == 2) ? fv.z : fv.w;
                const float* kr = &Ks[(fb + i) * NP + f0];
                float2 k0 = *(const float2*)(kr);
                float2 k1 = *(const float2*)(kr + 64);
                float2 k2 = *(const float2*)(kr + 128);
                float2 k3 = *(const float2*)(kr + 192);   // overreads for j>=199 are discarded later
                d0.x += fvi * k0.x; d0.y += fvi * k0.y;
                d1.x += fvi * k1.x; d1.y += fvi * k1.y;
                d2.x += fvi * k2.x; d2.y += fvi * k2.y;
                d3.x += fvi * k3.x; d3.y += fvi * k3.y;
            }
        }

        // ---------- masked softmax over j ----------
        const float* Arow = A + (size_t)m * NN;
        float dv[8] = {d0.x, d0.y, d1.x, d1.y, d2.x, d2.y, d3.x, d3.y};
        float lg[8];
        float mx = -1e30f;
        #pragma unroll
        for (int s = 0; s < 8; s++) {
            int j = (s >> 1) * 64 + f0 + (s & 1);
            float v = -1e30f;
            if (j < NN) {
                float a = __ldg(&Arow[j]);
                if (a != 0.f) v = dv[s] + b1s[j];
            }
            lg[s] = v;
            mx = fmaxf(mx, v);
        }
        #pragma unroll
        for (int o = 16; o; o >>= 1) mx = fmaxf(mx, __shfl_xor_sync(0xffffffffu, mx, o));
        float ssum = 0.f;
        float ev[8];
        #pragma unroll
        for (int s = 0; s < 8; s++) {
            float e = (lg[s] > -1e29f) ? __expf(lg[s] - mx) : 0.f;
            ev[s] = e; ssum += e;
        }
        #pragma unroll
        for (int o = 16; o; o >>= 1) ssum += __shfl_xor_sync(0xffffffffu, ssum, o);
        float inv = 1.0f / ssum;
        #pragma unroll
        for (int s = 0; s < 8; s++) {
            int j = (s >> 1) * 64 + f0 + (s & 1);
            if (j < NN) mr[j] = ev[s] * inv;
        }
        __syncwarp();

        // ---------- phase 3: node row  node[f] = sum_j mask[j]*X[j][f] ----------
        float2 na = make_float2(0.f, 0.f);
        #pragma unroll 5
        for (int c = 0; c < NP / 4; c++) {
            float4 wv = *(const float4*)&mr[c * 4];   // mr[NN]==0 pad
            int j = c * 4;
            float2 x;
            x = *(const float2*)&Xs[(j + 0) * FF + f0]; na.x += wv.x * x.x; na.y += wv.x * x.y;
            x = *(const float2*)&Xs[(j + 1) * FF + f0]; na.x += wv.y * x.x; na.y += wv.y * x.y;
            x = *(const float2*)&Xs[(j + 2) * FF + f0]; na.x += wv.z * x.x; na.y += wv.z * x.y;
            x = *(const float2*)&Xs[(j + 3) * FF + f0]; na.x += wv.w * x.x; na.y += wv.w * x.y;
        }
        nr[f0] = na.x; nr[f0 + 1] = na.y;
        __syncwarp();

        // ---------- phase 4: out row  out[u] = sum_f node[f]*fc[f][u] + bias2[u] ----------
        float2 oa = make_float2(0.f, 0.f);
        #pragma unroll 4
        for (int fb = 0; fb < FF; fb += 4) {
            float4 nv = *(const float4*)&nr[fb];
            #pragma unroll
            for (int i = 0; i < 4; i++) {
                float nvi = (i == 0) ? nv.x : (i == 1) ? nv.y : (i == 2) ? nv.z : nv.w;
                float2 f2 = *(const float2*)&fcs[(fb + i) * UU + f0];
                oa.x += nvi * f2.x; oa.y += nvi * f2.y;
            }
        }
        size_t ob = ((size_t)b * NN + m) * OUTC + h * UU;
        out[ob + f0]     = oa.x + b2s[f0];
        out[ob + f0 + 1] = oa.y + b2s[f0 + 1];

        if (h == HH - 1) {
            size_t mb = ((size_t)b * NN + m) * OUTC + HH * UU;
            for (int j = lane; j < NN; j += 32) out[mb + j] = mr[j];
        }
        __syncwarp();
    }
}

extern "C" void kernel_launch(void* const* d_in, const int* in_sizes, int n_in,
                              void* d_out, int out_size)
{
    const float* X       = (const float*)d_in[0];
    const float* A       = (const float*)d_in[1];
    const float* kernels = (const float*)d_in[2];
    const float* params  = (const float*)d_in[3];
    const float* fc      = (const float*)d_in[4];
    const float* bias1   = (const float*)d_in[5];
    const float* bias2   = (const float*)d_in[6];
    float* out = (float*)d_out;

    int B = in_sizes[0] / (NN * FF);   // 512

    // precompute AWT (idempotent, same-stream ordering before main kernel)
    {
        int total = HH * NN * NP;
        awt_kernel<<<(total + 255) / 256, 256>>>(A, params);
    }

    const int smemBytes = (NP*FF + FF*NP + FF*UU + 16*FF + 16*FF + 16*NP + NP + UU) * (int)sizeof(float);
    cudaFuncSetAttribute(gc_kernel, cudaFuncAttributeMaxDynamicSharedMemorySize, smemBytes);
    gc_kernel<<<B * HH, 512, smemBytes>>>(X, A, kernels, fc, bias1, bias2, out);
}

// round 2
// speedup vs baseline: 1.5371x; 1.5371x over previous
#include <cuda_runtime.h>
#include <math.h>

#define NN   199
#define NP   200            // padded row stride (16B-aligned float4 rows)
#define FF   64
#define UU   64
#define HH   4
#define OUTC (HH*UU + NN)   // 455
#define ROWS 4              // m-rows per warp (register blocking)
#define NWARP 16

// Precomputed transposed masked adjacency weights: AWT[h][m][n] = A[n][m]*params[h][n][m]
__device__ float g_AWT[HH * NN * NP];

__global__ void awt_kernel(const float* __restrict__ A, const float* __restrict__ params) {
    int idx = blockIdx.x * blockDim.x + threadIdx.x;
    const int total = HH * NN * NP;
    if (idx >= total) return;
    int n = idx % NP;
    int m = (idx / NP) % NN;
    int h = idx / (NP * NN);
    float v = 0.f;
    if (n < NN) v = A[n * NN + m] * params[((size_t)h * NN + n) * NN + m];
    g_AWT[idx] = v;
}

__device__ __forceinline__ float comp4(const float4& v, int i) {
    return (i == 0) ? v.x : (i == 1) ? v.y : (i == 2) ? v.z : v.w;
}

__global__ __launch_bounds__(512, 1)
void gc_kernel(const float* __restrict__ X, const float* __restrict__ A,
               const float* __restrict__ kernels, const float* __restrict__ fc,
               const float* __restrict__ bias1, const float* __restrict__ bias2,
               float* __restrict__ out)
{
    extern __shared__ float sm[];
    float* Xs   = sm;                         // [NP][FF]  (row NN zeroed)
    float* Ks   = Xs + NP * FF;               // [FF][NP]  (cols >=NN zeroed)
    float* fcs  = Ks + FF * NP;               // [FF][UU]
    float* rbuf = fcs + FF * UU;              // [NWARP][ROWS][FF]  feat/node overlay
    float* mrow = rbuf + NWARP * ROWS * FF;   // [NWARP][ROWS][NP]
    float* b1s  = mrow + NWARP * ROWS * NP;   // [NP]
    float* b2s  = b1s + NP;                   // [UU]

    const int bx   = blockIdx.x;
    const int h    = bx % HH;
    const int b    = bx / HH;
    const int tid  = threadIdx.x;
    const int lane = tid & 31;
    const int w    = tid >> 5;

    // ---------------- cooperative staging ----------------
    {
        const float4* Xg4 = (const float4*)(X + (size_t)b * NN * FF);
        float4* Xs4 = (float4*)Xs;
        #pragma unroll 1
        for (int i = tid; i < NN * FF / 4; i += 512) Xs4[i] = Xg4[i];
        for (int i = tid; i < FF; i += 512) Xs[NN * FF + i] = 0.f;   // zero pad row

        const float* Kg = kernels + (size_t)h * FF * NN;
        #pragma unroll 1
        for (int i = tid; i < FF * NP; i += 512) {
            int f = i / NP, j = i - f * NP;
            Ks[i] = (j < NN) ? Kg[f * NN + j] : 0.f;
        }
        const float4* fg4 = (const float4*)(fc + (size_t)h * FF * UU);
        float4* fcs4 = (float4*)fcs;
        for (int i = tid; i < FF * UU / 4; i += 512) fcs4[i] = fg4[i];

        for (int i = tid; i < NP; i += 512) b1s[i] = (i < NN) ? bias1[h * NN + i] : 0.f;
        for (int i = tid; i < UU; i += 512) b2s[i] = bias2[h * UU + i];
        // zero the pad element of every per-warp mask row (float4 tail read)
        for (int i = tid; i < NWARP * ROWS; i += 512) mrow[i * NP + NN] = 0.f;
    }
    __syncthreads();

    const int f0 = 2 * lane;
    float* fr = rbuf + (w * ROWS) * FF;       // [ROWS][FF]
    float* mr = mrow + (w * ROWS) * NP;       // [ROWS][NP]

    for (int mb = 0; mb < NN; mb += NWARP * ROWS) {
        const int m0 = mb + w * ROWS;

        // clamp row indices for safe (discarded) loads
        int mi[ROWS];
        #pragma unroll
        for (int r = 0; r < ROWS; r++) {
            int m = m0 + r;
            mi[r] = (m < NN) ? m : (NN - 1);
        }

        // ---------- phase 1: feat rows  feat[r][f] = sum_n AWT[m_r][n] * X[n][f] ----------
        const float4* aw4[ROWS];
        #pragma unroll
        for (int r = 0; r < ROWS; r++)
            aw4[r] = (const float4*)(g_AWT + ((size_t)h * NN + mi[r]) * NP);

        float2 fa[ROWS];
        #pragma unroll
        for (int r = 0; r < ROWS; r++) fa[r] = make_float2(0.f, 0.f);

        #pragma unroll 2
        for (int c = 0; c < NP / 4; c++) {
            float4 a[ROWS];
            #pragma unroll
            for (int r = 0; r < ROWS; r++) a[r] = __ldg(&aw4[r][c]);
            const int n = c * 4;
            #pragma unroll
            for (int q = 0; q < 4; q++) {
                float2 x = *(const float2*)&Xs[(n + q) * FF + f0];
                #pragma unroll
                for (int r = 0; r < ROWS; r++) {
                    float av = comp4(a[r], q);
                    fa[r].x += av * x.x; fa[r].y += av * x.y;
                }
            }
        }
        #pragma unroll
        for (int r = 0; r < ROWS; r++) {
            fr[r * FF + f0]     = fa[r].x;
            fr[r * FF + f0 + 1] = fa[r].y;
        }
        __syncwarp();

        // ---------- phase 2: dense rows  dense[r][j] = sum_f feat[r][f]*K[f][j] ----------
        // lane owns 8 j-slots per row: j = 64*k + f0 + i
        float2 d[ROWS][4];
        #pragma unroll
        for (int r = 0; r < ROWS; r++)
            #pragma unroll
            for (int k = 0; k < 4; k++) d[r][k] = make_float2(0.f, 0.f);

        #pragma unroll 2
        for (int fb = 0; fb < FF; fb += 4) {
            float4 fv[ROWS];
            #pragma unroll
            for (int r = 0; r < ROWS; r++) fv[r] = *(const float4*)&fr[r * FF + fb];
            #pragma unroll
            for (int i = 0; i < 4; i++) {
                const float* kr = &Ks[(fb + i) * NP + f0];
                float2 k0 = *(const float2*)(kr);
                float2 k1 = *(const float2*)(kr + 64);
                float2 k2 = *(const float2*)(kr + 128);
                float2 k3 = *(const float2*)(kr + 192);   // tail overread discarded via j<NN
                #pragma unroll
                for (int r = 0; r < ROWS; r++) {
                    float fvi = comp4(fv[r], i);
                    d[r][0].x += fvi * k0.x; d[r][0].y += fvi * k0.y;
                    d[r][1].x += fvi * k1.x; d[r][1].y += fvi * k1.y;
                    d[r][2].x += fvi * k2.x; d[r][2].y += fvi * k2.y;
                    d[r][3].x += fvi * k3.x; d[r][3].y += fvi * k3.y;
                }
            }
        }

        // ---------- masked softmax per row ----------
        #pragma unroll
        for (int r = 0; r < ROWS; r++) {
            const float* Arow = A + (size_t)mi[r] * NN;
            float dv[8] = {d[r][0].x, d[r][0].y, d[r][1].x, d[r][1].y,
                           d[r][2].x, d[r][2].y, d[r][3].x, d[r][3].y};
            float lg[8];
            float mx = -1e30f;
            #pragma unroll
            for (int s = 0; s < 8; s++) {
                int j = (s >> 1) * 64 + f0 + (s & 1);
                float v = -1e30f;
                if (j < NN) {
                    float a = __ldg(&Arow[j]);
                    if (a != 0.f) v = dv[s] + b1s[j];
                }
                lg[s] = v;
                mx = fmaxf(mx, v);
            }
            #pragma unroll
            for (int o = 16; o; o >>= 1) mx = fmaxf(mx, __shfl_xor_sync(0xffffffffu, mx, o));
            float ssum = 0.f;
            float ev[8];
            #pragma unroll
            for (int s = 0; s < 8; s++) {
                float e = (lg[s] > -1e29f) ? __expf(lg[s] - mx) : 0.f;
                ev[s] = e; ssum += e;
            }
            #pragma unroll
            for (int o = 16; o; o >>= 1) ssum += __shfl_xor_sync(0xffffffffu, ssum, o);
            float inv = 1.0f / ssum;
            #pragma unroll
            for (int s = 0; s < 8; s++) {
                int j = (s >> 1) * 64 + f0 + (s & 1);
                if (j < NN) mr[r * NP + j] = ev[s] * inv;
            }
        }
        __syncwarp();

        // ---------- phase 3: node rows  node[r][f] = sum_j mask[r][j]*X[j][f] ----------
        float2 na[ROWS];
        #pragma unroll
        for (int r = 0; r < ROWS; r++) na[r] = make_float2(0.f, 0.f);

        #pragma unroll 2
        for (int c = 0; c < NP / 4; c++) {
            float4 wv[ROWS];
            #pragma unroll
            for (int r = 0; r < ROWS; r++) wv[r] = *(const float4*)&mr[r * NP + c * 4];
            const int j = c * 4;
            #pragma unroll
            for (int q = 0; q < 4; q++) {
                float2 x = *(const float2*)&Xs[(j + q) * FF + f0];
                #pragma unroll
                for (int r = 0; r < ROWS; r++) {
                    float wvq = comp4(wv[r], q);
                    na[r].x += wvq * x.x; na[r].y += wvq * x.y;
                }
            }
        }
        __syncwarp();   // fr region dead; about to overwrite with node rows
        #pragma unroll
        for (int r = 0; r < ROWS; r++) {
            fr[r * FF + f0]     = na[r].x;
            fr[r * FF + f0 + 1] = na[r].y;
        }
        __syncwarp();

        // ---------- phase 4: out rows  out[r][u] = sum_f node[r][f]*fc[f][u] + bias2[u] ----------
        float2 oa[ROWS];
        #pragma unroll
        for (int r = 0; r < ROWS; r++) oa[r] = make_float2(0.f, 0.f);

        #pragma unroll 2
        for (int fb = 0; fb < FF; fb += 4) {
            float4 nv[ROWS];
            #pragma unroll
            for (int r = 0; r < ROWS; r++) nv[r] = *(const float4*)&fr[r * FF + fb];
            #pragma unroll
            for (int i = 0; i < 4; i++) {
                float2 f2 = *(const float2*)&fcs[(fb + i) * UU + f0];
                #pragma unroll
                for (int r = 0; r < ROWS; r++) {
                    float nvi = comp4(nv[r], i);
                    oa[r].x += nvi * f2.x; oa[r].y += nvi * f2.y;
                }
            }
        }

        #pragma unroll
        for (int r = 0; r < ROWS; r++) {
            int m = m0 + r;
            if (m < NN) {
                size_t ob = ((size_t)b * NN + m) * OUTC + h * UU;
                out[ob + f0]     = oa[r].x + b2s[f0];
                out[ob + f0 + 1] = oa[r].y + b2s[f0 + 1];
                if (h == HH - 1) {
                    size_t mb2 = ((size_t)b * NN + m) * OUTC + HH * UU;
                    for (int j = lane; j < NN; j += 32) out[mb2 + j] = mr[r * NP + j];
                }
            }
        }
        __syncwarp();
    }
}

extern "C" void kernel_launch(void* const* d_in, const int* in_sizes, int n_in,
                              void* d_out, int out_size)
{
    const float* X       = (const float*)d_in[0];
    const float* A       = (const float*)d_in[1];
    const float* kernels = (const float*)d_in[2];
    const float* params  = (const float*)d_in[3];
    const float* fc      = (const float*)d_in[4];
    const float* bias1   = (const float*)d_in[5];
    const float* bias2   = (const float*)d_in[6];
    float* out = (float*)d_out;

    int B = in_sizes[0] / (NN * FF);   // 512

    // precompute AWT (idempotent, same-stream ordering before main kernel)
    {
        int total = HH * NN * NP;
        awt_kernel<<<(total + 255) / 256, 256>>>(A, params);
    }

    const int smemBytes = (NP*FF + FF*NP + FF*UU + NWARP*ROWS*FF + NWARP*ROWS*NP + NP + UU) * (int)sizeof(float);
    cudaFuncSetAttribute(gc_kernel, cudaFuncAttributeMaxDynamicSharedMemorySize, smemBytes);
    gc_kernel<<<B * HH, 512, smemBytes>>>(X, A, kernels, fc, bias1, bias2, out);
}

// round 3
// speedup vs baseline: 1.8107x; 1.1779x over previous
#include <cuda_runtime.h>
#include <math.h>

#define NN   199
#define NP   200            // padded row stride (16B-aligned float4 rows)
#define FF   64
#define UU   64
#define HH   4
#define OUTC (HH*UU + NN)   // 455
#define ROWS 4              // m-rows per warp (register blocking)
#define NWARP 16

// Precomputed transposed masked adjacency weights: AWT[h][m][n] = A[n][m]*params[h][n][m]
__device__ float g_AWT[HH * NN * NP];

__global__ void awt_kernel(const float* __restrict__ A, const float* __restrict__ params) {
    int idx = blockIdx.x * blockDim.x + threadIdx.x;
    const int total = HH * NN * NP;
    if (idx >= total) return;
    int n = idx % NP;
    int m = (idx / NP) % NN;
    int h = idx / (NP * NN);
    float v = 0.f;
    if (n < NN) v = A[n * NN + m] * params[((size_t)h * NN + n) * NN + m];
    g_AWT[idx] = v;
}

__device__ __forceinline__ float comp4(const float4& v, int i) {
    return (i == 0) ? v.x : (i == 1) ? v.y : (i == 2) ? v.z : v.w;
}

__device__ __forceinline__ void fma_x2(unsigned long long& acc, unsigned long long a,
                                       unsigned long long b) {
    asm("fma.rn.f32x2 %0, %1, %2, %0;" : "+l"(acc) : "l"(a), "l"(b));
}
__device__ __forceinline__ unsigned long long pack_dup(float v) {
    unsigned long long p;
    asm("mov.b64 %0, {%1, %1};" : "=l"(p) : "f"(v));
    return p;
}

__global__ __launch_bounds__(512, 1)
void gc_kernel(const float* __restrict__ X, const float* __restrict__ A,
               const float* __restrict__ kernels, const float* __restrict__ fc,
               const float* __restrict__ bias1, const float* __restrict__ bias2,
               float* __restrict__ out)
{
    extern __shared__ float sm[];
    float* Xs   = sm;                         // [NP][FF]  (row NN zeroed)
    float* Ks   = Xs + NP * FF;               // [FF][NP]  (cols >=NN zeroed)
    float* fcs  = Ks + FF * NP;               // [FF][UU]
    float* rbuf = fcs + FF * UU;              // [NWARP][ROWS][FF]  feat/node overlay
    float* mrow = rbuf + NWARP * ROWS * FF;   // [NWARP][ROWS][NP]
    float* b1s  = mrow + NWARP * ROWS * NP;   // [NP]
    float* b2s  = b1s + NP;                   // [UU]

    const int bx   = blockIdx.x;
    const int h    = bx % HH;
    const int b    = bx / HH;
    const int tid  = threadIdx.x;
    const int lane = tid & 31;
    const int w    = tid >> 5;

    // ---------------- cooperative staging ----------------
    {
        const float4* Xg4 = (const float4*)(X + (size_t)b * NN * FF);
        float4* Xs4 = (float4*)Xs;
        #pragma unroll 1
        for (int i = tid; i < NN * FF / 4; i += 512) Xs4[i] = Xg4[i];
        for (int i = tid; i < FF; i += 512) Xs[NN * FF + i] = 0.f;   // zero pad row

        const float* Kg = kernels + (size_t)h * FF * NN;
        #pragma unroll 1
        for (int i = tid; i < FF * NP; i += 512) {
            int f = i / NP, j = i - f * NP;
            Ks[i] = (j < NN) ? Kg[f * NN + j] : 0.f;
        }
        const float4* fg4 = (const float4*)(fc + (size_t)h * FF * UU);
        float4* fcs4 = (float4*)fcs;
        for (int i = tid; i < FF * UU / 4; i += 512) fcs4[i] = fg4[i];

        for (int i = tid; i < NP; i += 512) b1s[i] = (i < NN) ? bias1[h * NN + i] : 0.f;
        for (int i = tid; i < UU; i += 512) b2s[i] = bias2[h * UU + i];
        // zero the pad element of every per-warp mask row (float4 tail read)
        for (int i = tid; i < NWARP * ROWS; i += 512) mrow[i * NP + NN] = 0.f;
    }
    __syncthreads();

    const int f0 = 2 * lane;
    float* fr = rbuf + (w * ROWS) * FF;       // [ROWS][FF]
    float* mr = mrow + (w * ROWS) * NP;       // [ROWS][NP]

    for (int mb = 0; mb < NN; mb += NWARP * ROWS) {
        const int m0 = mb + w * ROWS;
        if (m0 >= NN) continue;               // warp has no valid rows in this group

        // clamp row indices for safe (discarded) loads
        int mi[ROWS];
        #pragma unroll
        for (int r = 0; r < ROWS; r++) {
            int m = m0 + r;
            mi[r] = (m < NN) ? m : (NN - 1);
        }

        // ---------- phase 1: feat rows  feat[r][f] = sum_n AWT[m_r][n] * X[n][f] ----------
        const float4* aw4[ROWS];
        #pragma unroll
        for (int r = 0; r < ROWS; r++)
            aw4[r] = (const float4*)(g_AWT + ((size_t)h * NN + mi[r]) * NP);

        float2 fa[ROWS];
        #pragma unroll
        for (int r = 0; r < ROWS; r++) fa[r] = make_float2(0.f, 0.f);

        // distance-2 software pipeline on the AWT global loads (L2 ~234-262 cyc)
        float4 abuf[2][ROWS];
        #pragma unroll
        for (int r = 0; r < ROWS; r++) abuf[0][r] = __ldg(&aw4[r][0]);
        #pragma unroll
        for (int r = 0; r < ROWS; r++) abuf[1][r] = __ldg(&aw4[r][1]);

        #pragma unroll 2
        for (int c = 0; c < NP / 4; c++) {
            const int cur = c & 1;
            float4 a[ROWS];
            #pragma unroll
            for (int r = 0; r < ROWS; r++) a[r] = abuf[cur][r];
            if (c + 2 < NP / 4) {
                #pragma unroll
                for (int r = 0; r < ROWS; r++) abuf[cur][r] = __ldg(&aw4[r][c + 2]);
            }
            const int n = c * 4;
            #pragma unroll
            for (int q = 0; q < 4; q++) {
                float2 x = *(const float2*)&Xs[(n + q) * FF + f0];
                #pragma unroll
                for (int r = 0; r < ROWS; r++) {
                    float av = comp4(a[r], q);
                    fa[r].x += av * x.x; fa[r].y += av * x.y;
                }
            }
        }
        #pragma unroll
        for (int r = 0; r < ROWS; r++) {
            fr[r * FF + f0]     = fa[r].x;
            fr[r * FF + f0 + 1] = fa[r].y;
        }
        __syncwarp();

        // ---------- adjacency bit-mask prefetch (overlaps phase 2) ----------
        int amask[ROWS];
        #pragma unroll
        for (int r = 0; r < ROWS; r++) {
            const float* Arow = A + (size_t)mi[r] * NN;
            int msk = 0;
            #pragma unroll
            for (int s = 0; s < 8; s++) {
                int j = (s >> 1) * 64 + f0 + (s & 1);
                if (j < NN && __ldg(&Arow[j]) != 0.f) msk |= (1 << s);
            }
            amask[r] = msk;
        }

        // ---------- phase 2: dense rows  dense[r][j] = sum_f feat[r][f]*K[f][j] ----------
        // packed f32x2: pack the broadcast feat scalar once, reuse across 4 j-vectors
        unsigned long long dacc[ROWS][4];
        #pragma unroll
        for (int r = 0; r < ROWS; r++)
            #pragma unroll
            for (int k = 0; k < 4; k++) dacc[r][k] = 0ull;

        #pragma unroll 2
        for (int fb = 0; fb < FF; fb += 4) {
            float4 fv[ROWS];
            #pragma unroll
            for (int r = 0; r < ROWS; r++) fv[r] = *(const float4*)&fr[r * FF + fb];
            #pragma unroll
            for (int i = 0; i < 4; i++) {
                const float* kr = &Ks[(fb + i) * NP + f0];
                unsigned long long k0 = *(const unsigned long long*)(kr);
                unsigned long long k1 = *(const unsigned long long*)(kr + 64);
                unsigned long long k2 = *(const unsigned long long*)(kr + 128);
                unsigned long long k3 = *(const unsigned long long*)(kr + 192);
                #pragma unroll
                for (int r = 0; r < ROWS; r++) {
                    unsigned long long p = pack_dup(comp4(fv[r], i));
                    fma_x2(dacc[r][0], p, k0);
                    fma_x2(dacc[r][1], p, k1);
                    fma_x2(dacc[r][2], p, k2);
                    fma_x2(dacc[r][3], p, k3);
                }
            }
        }

        // ---------- masked softmax per row ----------
        #pragma unroll
        for (int r = 0; r < ROWS; r++) {
            float dv[8];
            #pragma unroll
            for (int k = 0; k < 4; k++)
                asm("mov.b64 {%0, %1}, %2;" : "=f"(dv[2*k]), "=f"(dv[2*k+1]) : "l"(dacc[r][k]));
            float lg[8];
            float mx = -1e30f;
            #pragma unroll
            for (int s = 0; s < 8; s++) {
                int j = (s >> 1) * 64 + f0 + (s & 1);
                float v = -1e30f;
                if (amask[r] & (1 << s)) v = dv[s] + b1s[j];
                lg[s] = v;
                mx = fmaxf(mx, v);
            }
            #pragma unroll
            for (int o = 16; o; o >>= 1) mx = fmaxf(mx, __shfl_xor_sync(0xffffffffu, mx, o));
            float ssum = 0.f;
            float ev[8];
            #pragma unroll
            for (int s = 0; s < 8; s++) {
                float e = (lg[s] > -1e29f) ? __expf(lg[s] - mx) : 0.f;
                ev[s] = e; ssum += e;
            }
            #pragma unroll
            for (int o = 16; o; o >>= 1) ssum += __shfl_xor_sync(0xffffffffu, ssum, o);
            float inv = 1.0f / ssum;
            #pragma unroll
            for (int s = 0; s < 8; s++) {
                int j = (s >> 1) * 64 + f0 + (s & 1);
                if (j < NN) mr[r * NP + j] = ev[s] * inv;
            }
        }
        __syncwarp();

        // ---------- phase 3: node rows  node[r][f] = sum_j mask[r][j]*X[j][f] ----------
        float2 na[ROWS];
        #pragma unroll
        for (int r = 0; r < ROWS; r++) na[r] = make_float2(0.f, 0.f);

        #pragma unroll 2
        for (int c = 0; c < NP / 4; c++) {
            float4 wv[ROWS];
            #pragma unroll
            for (int r = 0; r < ROWS; r++) wv[r] = *(const float4*)&mr[r * NP + c * 4];
            const int j = c * 4;
            #pragma unroll
            for (int q = 0; q < 4; q++) {
                float2 x = *(const float2*)&Xs[(j + q) * FF + f0];
                #pragma unroll
                for (int r = 0; r < ROWS; r++) {
                    float wvq = comp4(wv[r], q);
                    na[r].x += wvq * x.x; na[r].y += wvq * x.y;
                }
            }
        }
        __syncwarp();   // fr region dead; about to overwrite with node rows
        #pragma unroll
        for (int r = 0; r < ROWS; r++) {
            fr[r * FF + f0]     = na[r].x;
            fr[r * FF + f0 + 1] = na[r].y;
        }
        __syncwarp();

        // ---------- phase 4: out rows  out[r][u] = sum_f node[r][f]*fc[f][u] + bias2[u] ----------
        float2 oa[ROWS];
        #pragma unroll
        for (int r = 0; r < ROWS; r++) oa[r] = make_float2(0.f, 0.f);

        #pragma unroll 2
        for (int fb = 0; fb < FF; fb += 4) {
            float4 nv[ROWS];
            #pragma unroll
            for (int r = 0; r < ROWS; r++) nv[r] = *(const float4*)&fr[r * FF + fb];
            #pragma unroll
            for (int i = 0; i < 4; i++) {
                float2 f2 = *(const float2*)&fcs[(fb + i) * UU + f0];
                #pragma unroll
                for (int r = 0; r < ROWS; r++) {
                    float nvi = comp4(nv[r], i);
                    oa[r].x += nvi * f2.x; oa[r].y += nvi * f2.y;
                }
            }
        }

        #pragma unroll
        for (int r = 0; r < ROWS; r++) {
            int m = m0 + r;
            if (m < NN) {
                size_t ob = ((size_t)b * NN + m) * OUTC + h * UU;
                out[ob + f0]     = oa[r].x + b2s[f0];
                out[ob + f0 + 1] = oa[r].y + b2s[f0 + 1];
                if (h == HH - 1) {
                    size_t mb2 = ((size_t)b * NN + m) * OUTC + HH * UU;
                    for (int j = lane; j < NN; j += 32) out[mb2 + j] = mr[r * NP + j];
                }
            }
        }
        __syncwarp();
    }
}

extern "C" void kernel_launch(void* const* d_in, const int* in_sizes, int n_in,
                              void* d_out, int out_size)
{
    const float* X       = (const float*)d_in[0];
    const float* A       = (const float*)d_in[1];
    const float* kernels = (const float*)d_in[2];
    const float* params  = (const float*)d_in[3];
    const float* fc      = (const float*)d_in[4];
    const float* bias1   = (const float*)d_in[5];
    const float* bias2   = (const float*)d_in[6];
    float* out = (float*)d_out;

    int B = in_sizes[0] / (NN * FF);   // 512

    // precompute AWT (idempotent, same-stream ordering before main kernel)
    {
        int total = HH * NN * NP;
        awt_kernel<<<(total + 255) / 256, 256>>>(A, params);
    }

    const int smemBytes = (NP*FF + FF*NP + FF*UU + NWARP*ROWS*FF + NWARP*ROWS*NP + NP + UU) * (int)sizeof(float);
    cudaFuncSetAttribute(gc_kernel, cudaFuncAttributeMaxDynamicSharedMemorySize, smemBytes);
    gc_kernel<<<B * HH, 512, smemBytes>>>(X, A, kernels, fc, bias1, bias2, out);
}

// round 4
// speedup vs baseline: 2.1487x; 1.1867x over previous
#include <cuda_runtime.h>
#include <math.h>

#define NN   199
#define NP   200            // padded row stride (16B-aligned float4 rows)
#define FF   64
#define UU   64
#define HH   4
#define OUTC (HH*UU + NN)   // 455
#define ROWS 4              // m-rows per warp (register blocking)
#define NWARP 16
#define MAXD 96             // padded adjacency capacity (true max deg ~50)

// Compacted adjacency: for column m, entries {n, params[h][n][m]} for n with A[n][m]!=0,
// padded to MAXD with {NN, 0} (idx NN points at zeroed pad rows).
__device__ float2 g_adjv[HH * NN * MAXD];
__device__ int    g_deg[NN];

__global__ void adj_kernel(const float* __restrict__ A, const float* __restrict__ params) {
    int t = blockIdx.x * blockDim.x + threadIdx.x;   // t = h*NN + m
    if (t >= HH * NN) return;
    int h = t / NN, m = t - h * NN;
    float2* row = g_adjv + (size_t)t * MAXD;
    int k = 0;
    for (int n = 0; n < NN; n++) {
        if (A[n * NN + m] != 0.f) {
            if (k < MAXD) {
                float2 e;
                e.x = __int_as_float(n);
                e.y = params[((size_t)h * NN + n) * NN + m];
                row[k] = e;
            }
            k++;
        }
    }
    int deg = (k < MAXD) ? k : MAXD;
    for (int kk = deg; kk < MAXD; kk++) {
        float2 e; e.x = __int_as_float(NN); e.y = 0.f;
        row[kk] = e;
    }
    if (h == 0) g_deg[m] = deg;
}

__device__ __forceinline__ float comp4(const float4& v, int i) {
    return (i == 0) ? v.x : (i == 1) ? v.y : (i == 2) ? v.z : v.w;
}

__device__ __forceinline__ void fma_x2(unsigned long long& acc, unsigned long long a,
                                       unsigned long long b) {
    asm("fma.rn.f32x2 %0, %1, %2, %0;" : "+l"(acc) : "l"(a), "l"(b));
}
__device__ __forceinline__ unsigned long long pack_dup(float v) {
    unsigned long long p;
    asm("mov.b64 %0, {%1, %1};" : "=l"(p) : "f"(v));
    return p;
}

__global__ __launch_bounds__(512, 1)
void gc_kernel(const float* __restrict__ X, const float* __restrict__ A,
               const float* __restrict__ kernels, const float* __restrict__ fc,
               const float* __restrict__ bias1, const float* __restrict__ bias2,
               float* __restrict__ out)
{
    extern __shared__ float sm[];
    float* Xs   = sm;                         // [NP][FF]  (row NN zeroed)
    float* Ks   = Xs + NP * FF;               // [FF][NP]  (cols >=NN zeroed)
    float* fcs  = Ks + FF * NP;               // [FF][UU]
    float* rbuf = fcs + FF * UU;              // [NWARP][ROWS][FF]  feat/node overlay
    float* mrow = rbuf + NWARP * ROWS * FF;   // [NWARP][ROWS][NP]
    float* b1s  = mrow + NWARP * ROWS * NP;   // [NP]
    float* b2s  = b1s + NP;                   // [UU]

    const int bx   = blockIdx.x;
    const int h    = bx % HH;
    const int b    = bx / HH;
    const int tid  = threadIdx.x;
    const int lane = tid & 31;
    const int w    = tid >> 5;

    // ---------------- cooperative staging ----------------
    {
        const float4* Xg4 = (const float4*)(X + (size_t)b * NN * FF);
        float4* Xs4 = (float4*)Xs;
        #pragma unroll 1
        for (int i = tid; i < NN * FF / 4; i += 512) Xs4[i] = Xg4[i];
        for (int i = tid; i < FF; i += 512) Xs[NN * FF + i] = 0.f;   // zero pad row

        const float* Kg = kernels + (size_t)h * FF * NN;
        #pragma unroll 1
        for (int i = tid; i < FF * NP; i += 512) {
            int f = i / NP, j = i - f * NP;
            Ks[i] = (j < NN) ? Kg[f * NN + j] : 0.f;
        }
        const float4* fg4 = (const float4*)(fc + (size_t)h * FF * UU);
        float4* fcs4 = (float4*)fcs;
        for (int i = tid; i < FF * UU / 4; i += 512) fcs4[i] = fg4[i];

        for (int i = tid; i < NP; i += 512) b1s[i] = (i < NN) ? bias1[h * NN + i] : 0.f;
        for (int i = tid; i < UU; i += 512) b2s[i] = bias2[h * UU + i];
        // zero the pad element of every per-warp mask row
        for (int i = tid; i < NWARP * ROWS; i += 512) mrow[i * NP + NN] = 0.f;
    }
    __syncthreads();

    const int f0 = 2 * lane;
    float* fr = rbuf + (w * ROWS) * FF;       // [ROWS][FF]
    float* mr = mrow + (w * ROWS) * NP;       // [ROWS][NP]

    for (int mb = 0; mb < NN; mb += NWARP * ROWS) {
        const int m0 = mb + w * ROWS;
        if (m0 >= NN) continue;               // warp has no valid rows in this group

        int mi[ROWS];
        #pragma unroll
        for (int r = 0; r < ROWS; r++) {
            int m = m0 + r;
            mi[r] = (m < NN) ? m : (NN - 1);
        }

        // adjacency lists for the 4 rows; uniform loop bound = max degree
        const float2* av[ROWS];
        int deg4 = 0;
        #pragma unroll
        for (int r = 0; r < ROWS; r++) {
            av[r] = g_adjv + ((size_t)h * NN + mi[r]) * MAXD;
            int d = __ldg(&g_deg[mi[r]]);
            deg4 = max(deg4, d);
        }

        // ---------- phase 1 (sparse): feat[r][f] = sum_{n in adj(m_r)} p*X[n][f] ----------
        float2 fa[ROWS];
        #pragma unroll
        for (int r = 0; r < ROWS; r++) fa[r] = make_float2(0.f, 0.f);

        float2 vbuf[2][ROWS];
        #pragma unroll
        for (int r = 0; r < ROWS; r++) vbuf[0][r] = __ldg(&av[r][0]);
        #pragma unroll
        for (int r = 0; r < ROWS; r++) vbuf[1][r] = __ldg(&av[r][1]);

        #pragma unroll 2
        for (int k = 0; k < deg4; k++) {
            const int cur = k & 1;
            float2 v[ROWS];
            #pragma unroll
            for (int r = 0; r < ROWS; r++) v[r] = vbuf[cur][r];
            if (k + 2 < MAXD) {
                #pragma unroll
                for (int r = 0; r < ROWS; r++) vbuf[cur][r] = __ldg(&av[r][k + 2]);
            }
            #pragma unroll
            for (int r = 0; r < ROWS; r++) {
                int n = __float_as_int(v[r].x);          // NN pad -> zeroed row
                float2 x = *(const float2*)&Xs[n * FF + f0];
                fa[r].x += v[r].y * x.x; fa[r].y += v[r].y * x.y;
            }
        }
        #pragma unroll
        for (int r = 0; r < ROWS; r++) {
            fr[r * FF + f0]     = fa[r].x;
            fr[r * FF + f0 + 1] = fa[r].y;
        }
        __syncwarp();

        // ---------- adjacency bit-mask prefetch (overlaps phase 2) ----------
        int amask[ROWS];
        #pragma unroll
        for (int r = 0; r < ROWS; r++) {
            const float* Arow = A + (size_t)mi[r] * NN;
            int msk = 0;
            #pragma unroll
            for (int s = 0; s < 8; s++) {
                int j = (s >> 1) * 64 + f0 + (s & 1);
                if (j < NN && __ldg(&Arow[j]) != 0.f) msk |= (1 << s);
            }
            amask[r] = msk;
        }

        // ---------- phase 2 (dense): dense[r][j] = sum_f feat[r][f]*K[f][j] ----------
        unsigned long long dacc[ROWS][4];
        #pragma unroll
        for (int r = 0; r < ROWS; r++)
            #pragma unroll
            for (int k = 0; k < 4; k++) dacc[r][k] = 0ull;

        #pragma unroll 2
        for (int fb = 0; fb < FF; fb += 4) {
            float4 fv[ROWS];
            #pragma unroll
            for (int r = 0; r < ROWS; r++) fv[r] = *(const float4*)&fr[r * FF + fb];
            #pragma unroll
            for (int i = 0; i < 4; i++) {
                const float* kr = &Ks[(fb + i) * NP + f0];
                unsigned long long k0 = *(const unsigned long long*)(kr);
                unsigned long long k1 = *(const unsigned long long*)(kr + 64);
                unsigned long long k2 = *(const unsigned long long*)(kr + 128);
                unsigned long long k3 = *(const unsigned long long*)(kr + 192);
                #pragma unroll
                for (int r = 0; r < ROWS; r++) {
                    unsigned long long p = pack_dup(comp4(fv[r], i));
                    fma_x2(dacc[r][0], p, k0);
                    fma_x2(dacc[r][1], p, k1);
                    fma_x2(dacc[r][2], p, k2);
                    fma_x2(dacc[r][3], p, k3);
                }
            }
        }

        // ---------- masked softmax per row ----------
        #pragma unroll
        for (int r = 0; r < ROWS; r++) {
            float dv[8];
            #pragma unroll
            for (int k = 0; k < 4; k++)
                asm("mov.b64 {%0, %1}, %2;" : "=f"(dv[2*k]), "=f"(dv[2*k+1]) : "l"(dacc[r][k]));
            float lg[8];
            float mx = -1e30f;
            #pragma unroll
            for (int s = 0; s < 8; s++) {
                int j = (s >> 1) * 64 + f0 + (s & 1);
                float v = -1e30f;
                if (amask[r] & (1 << s)) v = dv[s] + b1s[j];
                lg[s] = v;
                mx = fmaxf(mx, v);
            }
            #pragma unroll
            for (int o = 16; o; o >>= 1) mx = fmaxf(mx, __shfl_xor_sync(0xffffffffu, mx, o));
            float ssum = 0.f;
            float ev[8];
            #pragma unroll
            for (int s = 0; s < 8; s++) {
                float e = (lg[s] > -1e29f) ? __expf(lg[s] - mx) : 0.f;
                ev[s] = e; ssum += e;
            }
            #pragma unroll
            for (int o = 16; o; o >>= 1) ssum += __shfl_xor_sync(0xffffffffu, ssum, o);
            float inv = 1.0f / ssum;
            #pragma unroll
            for (int s = 0; s < 8; s++) {
                int j = (s >> 1) * 64 + f0 + (s & 1);
                if (j < NN) mr[r * NP + j] = ev[s] * inv;
            }
        }
        __syncwarp();

        // ---------- phase 3 (sparse): node[r][f] = sum_{j in adj(m_r)} mask[r][j]*X[j][f] ----------
        float2 na[ROWS];
        #pragma unroll
        for (int r = 0; r < ROWS; r++) na[r] = make_float2(0.f, 0.f);

        #pragma unroll
        for (int r = 0; r < ROWS; r++) vbuf[0][r] = __ldg(&av[r][0]);
        #pragma unroll
        for (int r = 0; r < ROWS; r++) vbuf[1][r] = __ldg(&av[r][1]);

        #pragma unroll 2
        for (int k = 0; k < deg4; k++) {
            const int cur = k & 1;
            float2 v[ROWS];
            #pragma unroll
            for (int r = 0; r < ROWS; r++) v[r] = vbuf[cur][r];
            if (k + 2 < MAXD) {
                #pragma unroll
                for (int r = 0; r < ROWS; r++) vbuf[cur][r] = __ldg(&av[r][k + 2]);
            }
            #pragma unroll
            for (int r = 0; r < ROWS; r++) {
                int j = __float_as_int(v[r].x);          // NN pad -> mr[NN]==0, Xs pad row
                float mval = mr[r * NP + j];
                float2 x = *(const float2*)&Xs[j * FF + f0];
                na[r].x += mval * x.x; na[r].y += mval * x.y;
            }
        }
        __syncwarp();   // fr region dead; overwrite with node rows
        #pragma unroll
        for (int r = 0; r < ROWS; r++) {
            fr[r * FF + f0]     = na[r].x;
            fr[r * FF + f0 + 1] = na[r].y;
        }
        __syncwarp();

        // ---------- phase 4: out rows  out[r][u] = sum_f node[r][f]*fc[f][u] + bias2[u] ----------
        float2 oa[ROWS];
        #pragma unroll
        for (int r = 0; r < ROWS; r++) oa[r] = make_float2(0.f, 0.f);

        #pragma unroll 2
        for (int fb = 0; fb < FF; fb += 4) {
            float4 nv[ROWS];
            #pragma unroll
            for (int r = 0; r < ROWS; r++) nv[r] = *(const float4*)&fr[r * FF + fb];
            #pragma unroll
            for (int i = 0; i < 4; i++) {
                float2 f2 = *(const float2*)&fcs[(fb + i) * UU + f0];
                #pragma unroll
                for (int r = 0; r < ROWS; r++) {
                    float nvi = comp4(nv[r], i);
                    oa[r].x += nvi * f2.x; oa[r].y += nvi * f2.y;
                }
            }
        }

        #pragma unroll
        for (int r = 0; r < ROWS; r++) {
            int m = m0 + r;
            if (m < NN) {
                size_t ob = ((size_t)b * NN + m) * OUTC + h * UU;
                out[ob + f0]     = oa[r].x + b2s[f0];
                out[ob + f0 + 1] = oa[r].y + b2s[f0 + 1];
                if (h == HH - 1) {
                    size_t mb2 = ((size_t)b * NN + m) * OUTC + HH * UU;
                    for (int j = lane; j < NN; j += 32) out[mb2 + j] = mr[r * NP + j];
                }
            }
        }
        __syncwarp();
    }
}

extern "C" void kernel_launch(void* const* d_in, const int* in_sizes, int n_in,
                              void* d_out, int out_size)
{
    const float* X       = (const float*)d_in[0];
    const float* A       = (const float*)d_in[1];
    const float* kernels = (const float*)d_in[2];
    const float* params  = (const float*)d_in[3];
    const float* fc      = (const float*)d_in[4];
    const float* bias1   = (const float*)d_in[5];
    const float* bias2   = (const float*)d_in[6];
    float* out = (float*)d_out;

    int B = in_sizes[0] / (NN * FF);   // 512

    // build compacted adjacency (idempotent; ordered before main kernel on same stream)
    adj_kernel<<<(HH * NN + 255) / 256, 256>>>(A, params);

    const int smemBytes = (NP*FF + FF*NP + FF*UU + NWARP*ROWS*FF + NWARP*ROWS*NP + NP + UU) * (int)sizeof(float);
    cudaFuncSetAttribute(gc_kernel, cudaFuncAttributeMaxDynamicSharedMemorySize, smemBytes);
    gc_kernel<<<B * HH, 512, smemBytes>>>(X, A, kernels, fc, bias1, bias2, out);
}

// round 5
// speedup vs baseline: 2.1636x; 1.0070x over previous
#include <cuda_runtime.h>
#include <math.h>

#define NN   199
#define NP   200            // Xs/Ks padded row stride
#define MP   256            // mrow padded stride (q1 STS.128 never crosses rows)
#define FF   64
#define UU   64
#define HH   4
#define OUTC (HH*UU + NN)   // 455
#define ROWS 4              // m-rows per warp
#define NWARP 18
#define THREADS (NWARP*32)
#define MAXD 96             // padded adjacency capacity (true max deg ~50)

// Compacted adjacency: for column m, entries {n, params[h][n][m]} for n with A[n][m]!=0,
// padded to MAXD with {NN, 0} (idx NN points at zeroed pad rows).
__device__ float2   g_adjv[HH * NN * MAXD];
__device__ int      g_deg[NN];
__device__ unsigned g_abits[NN * 8];   // 256-bit adjacency mask per row m (bits >= NN clear)

__global__ void adj_kernel(const float* __restrict__ A, const float* __restrict__ params) {
    int t = blockIdx.x * blockDim.x + threadIdx.x;   // t = h*NN + m
    if (t >= HH * NN) return;
    int h = t / NN, m = t - h * NN;
    float2* row = g_adjv + (size_t)t * MAXD;
    int k = 0;
    for (int n = 0; n < NN; n++) {
        if (A[n * NN + m] != 0.f) {
            if (k < MAXD) {
                float2 e;
                e.x = __int_as_float(n);
                e.y = params[((size_t)h * NN + n) * NN + m];
                row[k] = e;
            }
            k++;
        }
    }
    int deg = (k < MAXD) ? k : MAXD;
    for (int kk = deg; kk < MAXD; kk++) {
        float2 e; e.x = __int_as_float(NN); e.y = 0.f;
        row[kk] = e;
    }
    if (h == 0) {
        g_deg[m] = deg;
        unsigned wbits[8] = {0,0,0,0,0,0,0,0};
        for (int j = 0; j < NN; j++)
            if (A[(size_t)m * NN + j] != 0.f) wbits[j >> 5] |= (1u << (j & 31));
        for (int wd = 0; wd < 8; wd++) g_abits[m * 8 + wd] = wbits[wd];
    }
}

__device__ __forceinline__ float comp4(const float4& v, int i) {
    return (i == 0) ? v.x : (i == 1) ? v.y : (i == 2) ? v.z : v.w;
}
__device__ __forceinline__ void fma_x2(unsigned long long& acc, unsigned long long a,
                                       unsigned long long b) {
    asm("fma.rn.f32x2 %0, %1, %2, %0;" : "+l"(acc) : "l"(a), "l"(b));
}
__device__ __forceinline__ unsigned long long pack_dup(float v) {
    unsigned long long p;
    asm("mov.b64 %0, {%1, %1};" : "=l"(p) : "f"(v));
    return p;
}

__global__ __launch_bounds__(THREADS, 1)
void gc_kernel(const float* __restrict__ X, const float* __restrict__ A,
               const float* __restrict__ kernels, const float* __restrict__ fc,
               const float* __restrict__ bias1, const float* __restrict__ bias2,
               float* __restrict__ out)
{
    extern __shared__ float sm[];
    float* Xs   = sm;                         // [NP][FF]  (row NN zeroed)
    float* Ks   = Xs + NP * FF;               // [FF][NP]  (cols >=NN zeroed)
    float* fcs  = Ks + FF * NP;               // [FF][UU]
    float* rbuf = fcs + FF * UU;              // [NWARP][ROWS][FF]  feat/node overlay
    float* mrow = rbuf + NWARP * ROWS * FF;   // [NWARP][ROWS][MP]
    float* b1s  = mrow + NWARP * ROWS * MP;   // [256] (pad >=NN zero)
    float* b2s  = b1s + MP;                   // [UU]

    const int bx   = blockIdx.x;
    const int h    = bx % HH;
    const int b    = bx / HH;
    const int tid  = threadIdx.x;
    const int lane = tid & 31;
    const int w    = tid >> 5;

    // ---------------- cooperative staging ----------------
    {
        const float4* Xg4 = (const float4*)(X + (size_t)b * NN * FF);
        float4* Xs4 = (float4*)Xs;
        #pragma unroll 1
        for (int i = tid; i < NN * FF / 4; i += THREADS) Xs4[i] = Xg4[i];
        for (int i = tid; i < FF; i += THREADS) Xs[NN * FF + i] = 0.f;   // zero pad row

        const float* Kg = kernels + (size_t)h * FF * NN;
        #pragma unroll 1
        for (int i = tid; i < FF * NP; i += THREADS) {
            int f = i / NP, j = i - f * NP;
            Ks[i] = (j < NN) ? Kg[f * NN + j] : 0.f;
        }
        const float4* fg4 = (const float4*)(fc + (size_t)h * FF * UU);
        float4* fcs4 = (float4*)fcs;
        for (int i = tid; i < FF * UU / 4; i += THREADS) fcs4[i] = fg4[i];

        for (int i = tid; i < MP; i += THREADS) b1s[i] = (i < NN) ? bias1[h * NN + i] : 0.f;
        for (int i = tid; i < UU; i += THREADS) b2s[i] = bias2[h * UU + i];
    }
    __syncthreads();

    const int f0 = 2 * lane;
    const int j0 = 4 * lane;
    float* fr = rbuf + (w * ROWS) * FF;       // [ROWS][FF]
    float* mr = mrow + (w * ROWS) * MP;       // [ROWS][MP]

    // hoisted bias1 for this lane's 8 j-slots
    const float4 b1q0 = *(const float4*)&b1s[j0];
    const float4 b1q1 = *(const float4*)&b1s[128 + j0];

    for (int mb = 0; mb < NN; mb += NWARP * ROWS) {
        const int m0 = mb + w * ROWS;
        if (m0 >= NN) continue;

        int mi[ROWS];
        #pragma unroll
        for (int r = 0; r < ROWS; r++) {
            int m = m0 + r;
            mi[r] = (m < NN) ? m : (NN - 1);
        }

        const float2* av[ROWS];
        int deg4 = 0;
        #pragma unroll
        for (int r = 0; r < ROWS; r++) {
            av[r] = g_adjv + ((size_t)h * NN + mi[r]) * MAXD;
            int d = __ldg(&g_deg[mi[r]]);
            deg4 = max(deg4, d);
        }

        // ---------- phase 1 (sparse): feat[r][f] = sum_{n in adj(m_r)} p*X[n][f] ----------
        float2 fa[ROWS];
        #pragma unroll
        for (int r = 0; r < ROWS; r++) fa[r] = make_float2(0.f, 0.f);

        float2 vbuf[2][ROWS];
        #pragma unroll
        for (int r = 0; r < ROWS; r++) vbuf[0][r] = __ldg(&av[r][0]);
        #pragma unroll
        for (int r = 0; r < ROWS; r++) vbuf[1][r] = __ldg(&av[r][1]);

        #pragma unroll 2
        for (int k = 0; k < deg4; k++) {
            const int cur = k & 1;
            float2 v[ROWS];
            #pragma unroll
            for (int r = 0; r < ROWS; r++) v[r] = vbuf[cur][r];
            if (k + 2 < MAXD) {
                #pragma unroll
                for (int r = 0; r < ROWS; r++) vbuf[cur][r] = __ldg(&av[r][k + 2]);
            }
            #pragma unroll
            for (int r = 0; r < ROWS; r++) {
                int n = __float_as_int(v[r].x);          // NN pad -> zeroed row
                float2 x = *(const float2*)&Xs[n * FF + f0];
                fa[r].x += v[r].y * x.x; fa[r].y += v[r].y * x.y;
            }
        }
        #pragma unroll
        for (int r = 0; r < ROWS; r++) {
            fr[r * FF + f0]     = fa[r].x;
            fr[r * FF + f0 + 1] = fa[r].y;
        }
        __syncwarp();

        // ---------- adjacency bitmask prefetch (overlaps phase 2) ----------
        unsigned aw0[ROWS], aw1[ROWS];
        #pragma unroll
        for (int r = 0; r < ROWS; r++) {
            const unsigned* ab = g_abits + mi[r] * 8;
            aw0[r] = __ldg(&ab[lane >> 3]);
            aw1[r] = __ldg(&ab[4 + (lane >> 3)]);
        }
        const int bsh = 4 * (lane & 7);

        // ---------- phase 2 (dense): dense[r][j] = sum_f feat[r][f]*K[f][j] ----------
        // lane owns j = j0..j0+3 (q0) and 128+j0..+3 (q1)
        unsigned long long dacc[ROWS][4];
        #pragma unroll
        for (int r = 0; r < ROWS; r++)
            #pragma unroll
            for (int k = 0; k < 4; k++) dacc[r][k] = 0ull;

        #pragma unroll 2
        for (int fb = 0; fb < FF; fb += 4) {
            float4 fv[ROWS];
            #pragma unroll
            for (int r = 0; r < ROWS; r++) fv[r] = *(const float4*)&fr[r * FF + fb];
            #pragma unroll
            for (int i = 0; i < 4; i++) {
                const float* kr = &Ks[(fb + i) * NP];
                ulonglong2 kq0 = *(const ulonglong2*)(kr + j0);        // LDS.128
                ulonglong2 kq1 = *(const ulonglong2*)(kr + 128 + j0);  // LDS.128 (tail overread discarded)
                #pragma unroll
                for (int r = 0; r < ROWS; r++) {
                    unsigned long long p = pack_dup(comp4(fv[r], i));
                    fma_x2(dacc[r][0], p, kq0.x);
                    fma_x2(dacc[r][1], p, kq0.y);
                    fma_x2(dacc[r][2], p, kq1.x);
                    fma_x2(dacc[r][3], p, kq1.y);
                }
            }
        }

        // ---------- masked softmax per row ----------
        #pragma unroll
        for (int r = 0; r < ROWS; r++) {
            float dv[8];
            #pragma unroll
            for (int k = 0; k < 4; k++)
                asm("mov.b64 {%0, %1}, %2;" : "=f"(dv[2*k]), "=f"(dv[2*k+1]) : "l"(dacc[r][k]));
            float lg[8];
            float mx = -1e30f;
            #pragma unroll
            for (int s = 0; s < 8; s++) {
                unsigned wbits = (s < 4) ? aw0[r] : aw1[r];
                float b1v = (s < 4) ? comp4(b1q0, s) : comp4(b1q1, s - 4);
                bool on = (wbits >> (bsh + (s & 3))) & 1u;
                float v = on ? (dv[s] + b1v) : -1e30f;
                lg[s] = v;
                mx = fmaxf(mx, v);
            }
            #pragma unroll
            for (int o = 16; o; o >>= 1) mx = fmaxf(mx, __shfl_xor_sync(0xffffffffu, mx, o));
            float ssum = 0.f;
            float ev[8];
            #pragma unroll
            for (int s = 0; s < 8; s++) {
                float e = (lg[s] > -1e29f) ? __expf(lg[s] - mx) : 0.f;
                ev[s] = e; ssum += e;
            }
            #pragma unroll
            for (int o = 16; o; o >>= 1) ssum += __shfl_xor_sync(0xffffffffu, ssum, o);
            float inv = 1.0f / ssum;
            float4 mv0 = make_float4(ev[0]*inv, ev[1]*inv, ev[2]*inv, ev[3]*inv);
            float4 mv1 = make_float4(ev[4]*inv, ev[5]*inv, ev[6]*inv, ev[7]*inv);
            *(float4*)&mr[r * MP + j0]       = mv0;   // STS.128
            *(float4*)&mr[r * MP + 128 + j0] = mv1;   // STS.128 (pad cols masked -> 0)
        }
        __syncwarp();

        // ---------- phase 3 (sparse): node[r][f] = sum_{j in adj(m_r)} mask[r][j]*X[j][f] ----------
        float2 na[ROWS];
        #pragma unroll
        for (int r = 0; r < ROWS; r++) na[r] = make_float2(0.f, 0.f);

        #pragma unroll
        for (int r = 0; r < ROWS; r++) vbuf[0][r] = __ldg(&av[r][0]);
        #pragma unroll
        for (int r = 0; r < ROWS; r++) vbuf[1][r] = __ldg(&av[r][1]);

        #pragma unroll 2
        for (int k = 0; k < deg4; k++) {
            const int cur = k & 1;
            float2 v[ROWS];
            #pragma unroll
            for (int r = 0; r < ROWS; r++) v[r] = vbuf[cur][r];
            if (k + 2 < MAXD) {
                #pragma unroll
                for (int r = 0; r < ROWS; r++) vbuf[cur][r] = __ldg(&av[r][k + 2]);
            }
            #pragma unroll
            for (int r = 0; r < ROWS; r++) {
                int j = __float_as_int(v[r].x);          // NN pad -> mr[..NN]==0, Xs pad row
                float mval = mr[r * MP + j];
                float2 x = *(const float2*)&Xs[j * FF + f0];
                na[r].x += mval * x.x; na[r].y += mval * x.y;
            }
        }
        __syncwarp();   // fr region dead; overwrite with node rows
        #pragma unroll
        for (int r = 0; r < ROWS; r++) {
            fr[r * FF + f0]     = na[r].x;
            fr[r * FF + f0 + 1] = na[r].y;
        }
        __syncwarp();

        // ---------- phase 4: out[r][u] = sum_f node[r][f]*fc[f][u] + bias2[u] ----------
        float2 oa[ROWS];
        #pragma unroll
        for (int r = 0; r < ROWS; r++) oa[r] = make_float2(0.f, 0.f);

        #pragma unroll 2
        for (int fb = 0; fb < FF; fb += 4) {
            float4 nv[ROWS];
            #pragma unroll
            for (int r = 0; r < ROWS; r++) nv[r] = *(const float4*)&fr[r * FF + fb];
            #pragma unroll
            for (int i = 0; i < 4; i++) {
                float2 f2 = *(const float2*)&fcs[(fb + i) * UU + f0];
                #pragma unroll
                for (int r = 0; r < ROWS; r++) {
                    float nvi = comp4(nv[r], i);
                    oa[r].x += nvi * f2.x; oa[r].y += nvi * f2.y;
                }
            }
        }

        #pragma unroll
        for (int r = 0; r < ROWS; r++) {
            int m = m0 + r;
            if (m < NN) {
                size_t ob = ((size_t)b * NN + m) * OUTC + h * UU;
                out[ob + f0]     = oa[r].x + b2s[f0];
                out[ob + f0 + 1] = oa[r].y + b2s[f0 + 1];
                if (h == HH - 1) {
                    size_t mb2 = ((size_t)b * NN + m) * OUTC + HH * UU;
                    for (int j = lane; j < NN; j += 32) out[mb2 + j] = mr[r * MP + j];
                }
            }
        }
        __syncwarp();
    }
}

extern "C" void kernel_launch(void* const* d_in, const int* in_sizes, int n_in,
                              void* d_out, int out_size)
{
    const float* X       = (const float*)d_in[0];
    const float* A       = (const float*)d_in[1];
    const float* kernels = (const float*)d_in[2];
    const float* params  = (const float*)d_in[3];
    const float* fc      = (const float*)d_in[4];
    const float* bias1   = (const float*)d_in[5];
    const float* bias2   = (const float*)d_in[6];
    float* out = (float*)d_out;

    int B = in_sizes[0] / (NN * FF);   // 512

    adj_kernel<<<(HH * NN + 255) / 256, 256>>>(A, params);

    const int smemBytes = (NP*FF + FF*NP + FF*UU + NWARP*ROWS*FF + NWARP*ROWS*MP + MP + UU) * (int)sizeof(float);
    cudaFuncSetAttribute(gc_kernel, cudaFuncAttributeMaxDynamicSharedMemorySize, smemBytes);
    gc_kernel<<<B * HH, THREADS, smemBytes>>>(X, A, kernels, fc, bias1, bias2, out);
}

// round 6
// speedup vs baseline: 2.1748x; 1.0052x over previous
#include <cuda_runtime.h>
#include <math.h>

#define NN   199
#define NP   200            // Xs/Ks padded row stride
#define MP   256            // mrow padded stride (q1 STS.128 never crosses rows)
#define FF   64
#define UU   64
#define HH   4
#define OUTC (HH*UU + NN)   // 455
#define ROWS 4              // m-rows per warp
#define NWARP 18
#define THREADS (NWARP*32)
#define MAXD 96             // padded adjacency capacity (true max deg ~50)

// Compacted adjacency: for column m, entries {n, params[h][n][m]} for n with A[n][m]!=0,
// padded to MAXD with {NN, 0} (idx NN points at zeroed pad rows).
__device__ float2   g_adjv[HH * NN * MAXD];
__device__ int      g_deg[NN];
__device__ unsigned g_abits[NN * 8];   // 256-bit adjacency mask per row m (bits >= NN clear)

__global__ void adj_kernel(const float* __restrict__ A, const float* __restrict__ params) {
    int t = blockIdx.x * blockDim.x + threadIdx.x;   // t = h*NN + m
    if (t >= HH * NN) return;
    int h = t / NN, m = t - h * NN;
    float2* row = g_adjv + (size_t)t * MAXD;
    int k = 0;
    for (int n = 0; n < NN; n++) {
        if (A[n * NN + m] != 0.f) {
            if (k < MAXD) {
                float2 e;
                e.x = __int_as_float(n);
                e.y = params[((size_t)h * NN + n) * NN + m];
                row[k] = e;
            }
            k++;
        }
    }
    int deg = (k < MAXD) ? k : MAXD;
    for (int kk = deg; kk < MAXD; kk++) {
        float2 e; e.x = __int_as_float(NN); e.y = 0.f;
        row[kk] = e;
    }
    if (h == 0) {
        g_deg[m] = deg;
        unsigned wbits[8] = {0,0,0,0,0,0,0,0};
        for (int j = 0; j < NN; j++)
            if (A[(size_t)m * NN + j] != 0.f) wbits[j >> 5] |= (1u << (j & 31));
        for (int wd = 0; wd < 8; wd++) g_abits[m * 8 + wd] = wbits[wd];
    }
}

__device__ __forceinline__ float comp4(const float4& v, int i) {
    return (i == 0) ? v.x : (i == 1) ? v.y : (i == 2) ? v.z : v.w;
}
__device__ __forceinline__ void fma_x2(unsigned long long& acc, unsigned long long a,
                                       unsigned long long b) {
    asm("fma.rn.f32x2 %0, %1, %2, %0;" : "+l"(acc) : "l"(a), "l"(b));
}
__device__ __forceinline__ unsigned long long pack_dup(float v) {
    unsigned long long p;
    asm("mov.b64 %0, {%1, %1};" : "=l"(p) : "f"(v));
    return p;
}

__global__ __launch_bounds__(THREADS, 1)
void gc_kernel(const float* __restrict__ X, const float* __restrict__ A,
               const float* __restrict__ kernels, const float* __restrict__ fc,
               const float* __restrict__ bias1, const float* __restrict__ bias2,
               float* __restrict__ out)
{
    extern __shared__ float sm[];
    float* Xs   = sm;                         // [NP][FF]  (row NN zeroed)
    float* Ks   = Xs + NP * FF;               // [FF][NP]  (cols >=NN zeroed)
    float* fcs  = Ks + FF * NP;               // [FF][UU]
    float* rbuf = fcs + FF * UU;              // [NWARP][ROWS][FF]  feat/node overlay
    float* mrow = rbuf + NWARP * ROWS * FF;   // [NWARP][ROWS][MP]
    float* b1s  = mrow + NWARP * ROWS * MP;   // [256] (pad >=NN zero)
    float* b2s  = b1s + MP;                   // [UU]

    const int bx   = blockIdx.x;
    const int h    = bx % HH;
    const int b    = bx / HH;
    const int tid  = threadIdx.x;
    const int lane = tid & 31;
    const int w    = tid >> 5;

    // ---------------- cooperative staging ----------------
    {
        const float4* Xg4 = (const float4*)(X + (size_t)b * NN * FF);
        float4* Xs4 = (float4*)Xs;
        #pragma unroll 1
        for (int i = tid; i < NN * FF / 4; i += THREADS) Xs4[i] = Xg4[i];
        for (int i = tid; i < FF; i += THREADS) Xs[NN * FF + i] = 0.f;   // zero pad row

        const float* Kg = kernels + (size_t)h * FF * NN;
        #pragma unroll 1
        for (int i = tid; i < FF * NP; i += THREADS) {
            int f = i / NP, j = i - f * NP;
            Ks[i] = (j < NN) ? Kg[f * NN + j] : 0.f;
        }
        const float4* fg4 = (const float4*)(fc + (size_t)h * FF * UU);
        float4* fcs4 = (float4*)fcs;
        for (int i = tid; i < FF * UU / 4; i += THREADS) fcs4[i] = fg4[i];

        for (int i = tid; i < MP; i += THREADS) b1s[i] = (i < NN) ? bias1[h * NN + i] : 0.f;
        for (int i = tid; i < UU; i += THREADS) b2s[i] = bias2[h * UU + i];
    }
    __syncthreads();

    const int f0 = 2 * lane;
    const int j0 = 4 * lane;
    float* fr = rbuf + (w * ROWS) * FF;       // [ROWS][FF]
    float* mr = mrow + (w * ROWS) * MP;       // [ROWS][MP]

    // hoisted bias1 for this lane's 8 j-slots
    const float4 b1q0 = *(const float4*)&b1s[j0];
    const float4 b1q1 = *(const float4*)&b1s[128 + j0];

    for (int mb = 0; mb < NN; mb += NWARP * ROWS) {
        const int m0 = mb + w * ROWS;
        if (m0 >= NN) continue;

        int mi[ROWS];
        #pragma unroll
        for (int r = 0; r < ROWS; r++) {
            int m = m0 + r;
            mi[r] = (m < NN) ? m : (NN - 1);
        }

        const float2* av[ROWS];
        int deg4 = 0;
        #pragma unroll
        for (int r = 0; r < ROWS; r++) {
            av[r] = g_adjv + ((size_t)h * NN + mi[r]) * MAXD;
            int d = __ldg(&g_deg[mi[r]]);
            deg4 = max(deg4, d);
        }

        // ---------- phase 1 (sparse): feat[r][f] = sum_{n in adj(m_r)} p*X[n][f] ----------
        float2 fa[ROWS];
        #pragma unroll
        for (int r = 0; r < ROWS; r++) fa[r] = make_float2(0.f, 0.f);

        float2 vbuf[2][ROWS];
        #pragma unroll
        for (int r = 0; r < ROWS; r++) vbuf[0][r] = __ldg(&av[r][0]);
        #pragma unroll
        for (int r = 0; r < ROWS; r++) vbuf[1][r] = __ldg(&av[r][1]);

        #pragma unroll 2
        for (int k = 0; k < deg4; k++) {
            const int cur = k & 1;
            float2 v[ROWS];
            #pragma unroll
            for (int r = 0; r < ROWS; r++) v[r] = vbuf[cur][r];
            if (k + 2 < MAXD) {
                #pragma unroll
                for (int r = 0; r < ROWS; r++) vbuf[cur][r] = __ldg(&av[r][k + 2]);
            }
            #pragma unroll
            for (int r = 0; r < ROWS; r++) {
                int n = __float_as_int(v[r].x);          // NN pad -> zeroed row
                float2 x = *(const float2*)&Xs[n * FF + f0];
                fa[r].x += v[r].y * x.x; fa[r].y += v[r].y * x.y;
            }
        }
        #pragma unroll
        for (int r = 0; r < ROWS; r++) {
            fr[r * FF + f0]     = fa[r].x;
            fr[r * FF + f0 + 1] = fa[r].y;
        }
        __syncwarp();

        // ---------- adjacency bitmask prefetch (overlaps phase 2) ----------
        unsigned aw0[ROWS], aw1[ROWS];
        #pragma unroll
        for (int r = 0; r < ROWS; r++) {
            const unsigned* ab = g_abits + mi[r] * 8;
            aw0[r] = __ldg(&ab[lane >> 3]);
            aw1[r] = __ldg(&ab[4 + (lane >> 3)]);
        }
        const int bsh = 4 * (lane & 7);

        // ---------- phase 2 (dense): dense[r][j] = sum_f feat[r][f]*K[f][j] ----------
        // lane owns j = j0..j0+3 (q0) and 128+j0..+3 (q1)
        unsigned long long dacc[ROWS][4];
        #pragma unroll
        for (int r = 0; r < ROWS; r++)
            #pragma unroll
            for (int k = 0; k < 4; k++) dacc[r][k] = 0ull;

        #pragma unroll 2
        for (int fb = 0; fb < FF; fb += 4) {
            float4 fv[ROWS];
            #pragma unroll
            for (int r = 0; r < ROWS; r++) fv[r] = *(const float4*)&fr[r * FF + fb];
            #pragma unroll
            for (int i = 0; i < 4; i++) {
                const float* kr = &Ks[(fb + i) * NP];
                ulonglong2 kq0 = *(const ulonglong2*)(kr + j0);        // LDS.128
                ulonglong2 kq1 = *(const ulonglong2*)(kr + 128 + j0);  // LDS.128 (tail overread discarded)
                #pragma unroll
                for (int r = 0; r < ROWS; r++) {
                    unsigned long long p = pack_dup(comp4(fv[r], i));
                    fma_x2(dacc[r][0], p, kq0.x);
                    fma_x2(dacc[r][1], p, kq0.y);
                    fma_x2(dacc[r][2], p, kq1.x);
                    fma_x2(dacc[r][3], p, kq1.y);
                }
            }
        }

        // ---------- masked softmax per row ----------
        #pragma unroll
        for (int r = 0; r < ROWS; r++) {
            float dv[8];
            #pragma unroll
            for (int k = 0; k < 4; k++)
                asm("mov.b64 {%0, %1}, %2;" : "=f"(dv[2*k]), "=f"(dv[2*k+1]) : "l"(dacc[r][k]));
            float lg[8];
            float mx = -1e30f;
            #pragma unroll
            for (int s = 0; s < 8; s++) {
                unsigned wbits = (s < 4) ? aw0[r] : aw1[r];
                float b1v = (s < 4) ? comp4(b1q0, s) : comp4(b1q1, s - 4);
                bool on = (wbits >> (bsh + (s & 3))) & 1u;
                float v = on ? (dv[s] + b1v) : -1e30f;
                lg[s] = v;
                mx = fmaxf(mx, v);
            }
            #pragma unroll
            for (int o = 16; o; o >>= 1) mx = fmaxf(mx, __shfl_xor_sync(0xffffffffu, mx, o));
            float ssum = 0.f;
            float ev[8];
            #pragma unroll
            for (int s = 0; s < 8; s++) {
                float e = (lg[s] > -1e29f) ? __expf(lg[s] - mx) : 0.f;
                ev[s] = e; ssum += e;
            }
            #pragma unroll
            for (int o = 16; o; o >>= 1) ssum += __shfl_xor_sync(0xffffffffu, ssum, o);
            float inv = 1.0f / ssum;
            float4 mv0 = make_float4(ev[0]*inv, ev[1]*inv, ev[2]*inv, ev[3]*inv);
            float4 mv1 = make_float4(ev[4]*inv, ev[5]*inv, ev[6]*inv, ev[7]*inv);
            *(float4*)&mr[r * MP + j0]       = mv0;   // STS.128
            *(float4*)&mr[r * MP + 128 + j0] = mv1;   // STS.128 (pad cols masked -> 0)
        }
        __syncwarp();

        // ---------- phase 3 (sparse): node[r][f] = sum_{j in adj(m_r)} mask[r][j]*X[j][f] ----------
        float2 na[ROWS];
        #pragma unroll
        for (int r = 0; r < ROWS; r++) na[r] = make_float2(0.f, 0.f);

        #pragma unroll
        for (int r = 0; r < ROWS; r++) vbuf[0][r] = __ldg(&av[r][0]);
        #pragma unroll
        for (int r = 0; r < ROWS; r++) vbuf[1][r] = __ldg(&av[r][1]);

        #pragma unroll 2
        for (int k = 0; k < deg4; k++) {
            const int cur = k & 1;
            float2 v[ROWS];
            #pragma unroll
            for (int r = 0; r < ROWS; r++) v[r] = vbuf[cur][r];
            if (k + 2 < MAXD) {
                #pragma unroll
                for (int r = 0; r < ROWS; r++) vbuf[cur][r] = __ldg(&av[r][k + 2]);
            }
            #pragma unroll
            for (int r = 0; r < ROWS; r++) {
                int j = __float_as_int(v[r].x);          // NN pad -> mr[..NN]==0, Xs pad row
                float mval = mr[r * MP + j];
                float2 x = *(const float2*)&Xs[j * FF + f0];
                na[r].x += mval * x.x; na[r].y += mval * x.y;
            }
        }
        __syncwarp();   // fr region dead; overwrite with node rows
        #pragma unroll
        for (int r = 0; r < ROWS; r++) {
            fr[r * FF + f0]     = na[r].x;
            fr[r * FF + f0 + 1] = na[r].y;
        }
        __syncwarp();

        // ---------- phase 4: out[r][u] = sum_f node[r][f]*fc[f][u] + bias2[u] ----------
        float2 oa[ROWS];
        #pragma unroll
        for (int r = 0; r < ROWS; r++) oa[r] = make_float2(0.f, 0.f);

        #pragma unroll 2
        for (int fb = 0; fb < FF; fb += 4) {
            float4 nv[ROWS];
            #pragma unroll
            for (int r = 0; r < ROWS; r++) nv[r] = *(const float4*)&fr[r * FF + fb];
            #pragma unroll
            for (int i = 0; i < 4; i++) {
                float2 f2 = *(const float2*)&fcs[(fb + i) * UU + f0];
                #pragma unroll
                for (int r = 0; r < ROWS; r++) {
                    float nvi = comp4(nv[r], i);
                    oa[r].x += nvi * f2.x; oa[r].y += nvi * f2.y;
                }
            }
        }

        #pragma unroll
        for (int r = 0; r < ROWS; r++) {
            int m = m0 + r;
            if (m < NN) {
                size_t ob = ((size_t)b * NN + m) * OUTC + h * UU;
                out[ob + f0]     = oa[r].x + b2s[f0];
                out[ob + f0 + 1] = oa[r].y + b2s[f0 + 1];
                if (h == HH - 1) {
                    size_t mb2 = ((size_t)b * NN + m) * OUTC + HH * UU;
                    for (int j = lane; j < NN; j += 32) out[mb2 + j] = mr[r * MP + j];
                }
            }
        }
        __syncwarp();
    }
}

extern "C" void kernel_launch(void* const* d_in, const int* in_sizes, int n_in,
                              void* d_out, int out_size)
{
    const float* X       = (const float*)d_in[0];
    const float* A       = (const float*)d_in[1];
    const float* kernels = (const float*)d_in[2];
    const float* params  = (const float*)d_in[3];
    const float* fc      = (const float*)d_in[4];
    const float* bias1   = (const float*)d_in[5];
    const float* bias2   = (const float*)d_in[6];
    float* out = (float*)d_out;

    int B = in_sizes[0] / (NN * FF);   // 512

    adj_kernel<<<(HH * NN + 255) / 256, 256>>>(A, params);

    const int smemBytes = (NP*FF + FF*NP + FF*UU + NWARP*ROWS*FF + NWARP*ROWS*MP + MP + UU) * (int)sizeof(float);
    cudaFuncSetAttribute(gc_kernel, cudaFuncAttributeMaxDynamicSharedMemorySize, smemBytes);
    gc_kernel<<<B * HH, THREADS, smemBytes>>>(X, A, kernels, fc, bias1, bias2, out);
}

// round 8
// speedup vs baseline: 2.1756x; 1.0004x over previous
#include <cuda_runtime.h>
#include <cuda_fp16.h>
#include <math.h>

#define NN   199
#define NP   200
#define MP   208
#define FF   64
#define UU   64
#define HH   4
#define OUTC (HH*UU + NN)
#define ROWS 4
#define NWARP 18
#define THREADS (NWARP*32)
#define MAXD 96

// Compacted adjacency: for column m, entries {n, params[h][n][m]} for n with A[n][m]!=0,
// padded to MAXD with {NN, 0} (idx NN points at zeroed pad rows).
__device__ float2   g_adjv[HH * NN * MAXD];
__device__ int      g_deg[NN];
__device__ unsigned g_abits[NN * 8];

__global__ void adj_kernel(const float* __restrict__ A, const float* __restrict__ params) {
    int t = blockIdx.x * blockDim.x + threadIdx.x;
    if (t >= HH * NN) return;
    int h = t / NN, m = t - h * NN;
    float2* row = g_adjv + (size_t)t * MAXD;
    int k = 0;
    for (int n = 0; n < NN; n++) {
        if (A[n * NN + m] != 0.f) {
            if (k < MAXD) {
                float2 e;
                e.x = __int_as_float(n);
                e.y = params[((size_t)h * NN + n) * NN + m];
                row[k] = e;
            }
            k++;
        }
    }
    int deg = (k < MAXD) ? k : MAXD;
    for (int kk = deg; kk < MAXD; kk++) {
        float2 e; e.x = __int_as_float(NN); e.y = 0.f;
        row[kk] = e;
    }
    if (h == 0) {
        g_deg[m] = deg;
        unsigned wb[8] = {0,0,0,0,0,0,0,0};
        for (int j = 0; j < NN; j++)
            if (A[(size_t)m * NN + j] != 0.f) wb[j >> 5] |= (1u << (j & 31));
        for (int wd = 0; wd < 8; wd++) g_abits[m * 8 + wd] = wb[wd];
    }
}

__device__ __forceinline__ float comp4(const float4& v, int i) {
    return (i == 0) ? v.x : (i == 1) ? v.y : (i == 2) ? v.z : v.w;
}

__global__ __launch_bounds__(THREADS, 1)
void gc_kernel(const float* __restrict__ X, const float* __restrict__ A,
               const float* __restrict__ kernels, const float* __restrict__ fc,
               const float* __restrict__ bias1, const float* __restrict__ bias2,
               float* __restrict__ out)
{
    extern __shared__ float sm[];
    float*    Xs   = sm;                                    // [NP][FF] fp32 (row NN zeroed)
    unsigned* Xh2  = (unsigned*)(Xs + NP * FF);             // [NP][32] half2 (row NN zero)
    __half2*  Ksh  = (__half2*)(Xh2 + NP * 32);             // [FF][128] half2  (32 KB)
    float*    fcs  = (float*)(Ksh + FF * 128);              // [FF][UU] fp32
    float*    nbuf = fcs + FF * UU;                         // [NWARP][ROWS][FF] node fp32
    unsigned* frh  = (unsigned*)(nbuf + NWARP * ROWS * FF); // [NWARP][ROWS][32] feat half2
    float*    mrow = (float*)(frh + NWARP * ROWS * 32);     // [NWARP][ROWS][MP]
    float*    b1s  = mrow + NWARP * ROWS * MP;              // [256] (pad zero)
    float*    b2s  = b1s + 256;                             // [UU]

    const int bx   = blockIdx.x;
    const int h    = bx % HH;
    const int b    = bx / HH;
    const int tid  = threadIdx.x;
    const int lane = tid & 31;
    const int w    = tid >> 5;

    // ---------------- cooperative staging ----------------
    {
        const float* Xg = X + (size_t)b * NN * FF;
        const float4* Xg4 = (const float4*)Xg;
        float4* Xs4 = (float4*)Xs;
        #pragma unroll 1
        for (int i = tid; i < NN * FF / 4; i += THREADS) Xs4[i] = Xg4[i];
        for (int i = tid; i < FF; i += THREADS) Xs[NN * FF + i] = 0.f;

        #pragma unroll 1
        for (int i = tid; i < NP * 32; i += THREADS) {      // fp16 shadow of X
            int n = i >> 5, c = i & 31;
            float2 v = make_float2(0.f, 0.f);
            if (n < NN) v = *(const float2*)&Xg[n * FF + 2 * c];
            __half2 hv = __floats2half2_rn(v.x, v.y);
            Xh2[i] = *(unsigned*)&hv;
        }

        const float* Kg = kernels + (size_t)h * FF * NN;
        #pragma unroll 1
        for (int i = tid; i < FF * 128; i += THREADS) {     // fp16 K, [f][j] (j pairs)
            int f = i >> 7, jh = i & 127, j = 2 * jh;
            float a = (j < NN)     ? Kg[f * NN + j]     : 0.f;
            float c = (j + 1 < NN) ? Kg[f * NN + j + 1] : 0.f;
            Ksh[i] = __floats2half2_rn(a, c);
        }

        const float4* fg4 = (const float4*)(fc + (size_t)h * FF * UU);
        float4* fcs4 = (float4*)fcs;
        for (int i = tid; i < FF * UU / 4; i += THREADS) fcs4[i] = fg4[i];
        for (int i = tid; i < 256; i += THREADS) b1s[i] = (i < NN) ? bias1[h * NN + i] : 0.f;
        for (int i = tid; i < UU; i += THREADS) b2s[i] = bias2[h * UU + i];
    }
    __syncthreads();

    const int f0 = 2 * lane;
    const int j0 = 4 * lane;
    float*    nr = nbuf + (w * ROWS) * FF;
    unsigned* fw = frh  + (w * ROWS) * 32;
    float*    mr = mrow + (w * ROWS) * MP;

    const float4 b1q0 = *(const float4*)&b1s[j0];
    const float4 b1q1 = *(const float4*)&b1s[128 + j0];
    const __half2 hz = __float2half2_rn(0.f);

    for (int mb = 0; mb < NN; mb += NWARP * ROWS) {
        const int m0 = mb + w * ROWS;
        if (m0 >= NN) continue;

        int mi[ROWS];
        #pragma unroll
        for (int r = 0; r < ROWS; r++) {
            int m = m0 + r;
            mi[r] = (m < NN) ? m : (NN - 1);
        }

        const float2* av[ROWS];
        int deg4 = 0;
        #pragma unroll
        for (int r = 0; r < ROWS; r++) {
            av[r] = g_adjv + ((size_t)h * NN + mi[r]) * MAXD;
            deg4 = max(deg4, __ldg(&g_deg[mi[r]]));
        }

        // ---------- phase 1 (sparse, fp16 X, fp32 accum) ----------
        float2 fa[ROWS];
        #pragma unroll
        for (int r = 0; r < ROWS; r++) fa[r] = make_float2(0.f, 0.f);

        float2 vbuf[2][ROWS];
        #pragma unroll
        for (int r = 0; r < ROWS; r++) vbuf[0][r] = __ldg(&av[r][0]);
        #pragma unroll
        for (int r = 0; r < ROWS; r++) vbuf[1][r] = __ldg(&av[r][1]);

        #pragma unroll 2
        for (int k = 0; k < deg4; k++) {
            const int cur = k & 1;
            float2 v[ROWS];
            #pragma unroll
            for (int r = 0; r < ROWS; r++) v[r] = vbuf[cur][r];
            if (k + 2 < MAXD) {
                #pragma unroll
                for (int r = 0; r < ROWS; r++) vbuf[cur][r] = __ldg(&av[r][k + 2]);
            }
            #pragma unroll
            for (int r = 0; r < ROWS; r++) {
                int n = __float_as_int(v[r].x);
                unsigned xu = Xh2[n * 32 + lane];
                float2 xf = __half22float2(*(__half2*)&xu);
                fa[r].x += v[r].y * xf.x; fa[r].y += v[r].y * xf.y;
            }
        }
        #pragma unroll
        for (int r = 0; r < ROWS; r++) {
            __half2 hv = __floats2half2_rn(fa[r].x, fa[r].y);
            fw[r * 32 + lane] = *(unsigned*)&hv;
        }
        __syncwarp();

        // adjacency bitmask (overlaps phase 2)
        unsigned aw0[ROWS], aw1[ROWS];
        #pragma unroll
        for (int r = 0; r < ROWS; r++) {
            const unsigned* ab = g_abits + mi[r] * 8;
            aw0[r] = __ldg(&ab[lane >> 3]);
            aw1[r] = __ldg(&ab[4 + (lane >> 3)]);
        }
        const int bsh = 4 * (lane & 7);

        // ---------- phase 2 (dense, HFMA2, fp32 flush every 16 f) ----------
        float dsum[ROWS][8];
        __half2 hacc[ROWS][4];
        #pragma unroll
        for (int r = 0; r < ROWS; r++) {
            #pragma unroll
            for (int s = 0; s < 8; s++) dsum[r][s] = 0.f;
            #pragma unroll
            for (int k = 0; k < 4; k++) hacc[r][k] = hz;
        }

        #pragma unroll
        for (int chunk = 0; chunk < 4; chunk++) {
            #pragma unroll
            for (int fbq = 0; fbq < 4; fbq++) {
                const int fb = chunk * 16 + fbq * 4;
                uint2 fv[ROWS];
                #pragma unroll
                for (int r = 0; r < ROWS; r++) fv[r] = *(const uint2*)&fw[r * 32 + (fb >> 1)];
                #pragma unroll
                for (int i = 0; i < 4; i++) {
                    const __half2* kr = Ksh + (fb + i) * 128;
                    uint2 kq0 = *(const uint2*)(kr + 2 * lane);
                    uint2 kq1 = *(const uint2*)(kr + 64 + 2 * lane);
                    __half2 k0a = *(__half2*)&kq0.x, k0b = *(__half2*)&kq0.y;
                    __half2 k1a = *(__half2*)&kq1.x, k1b = *(__half2*)&kq1.y;
                    #pragma unroll
                    for (int r = 0; r < ROWS; r++) {
                        unsigned hv = (i < 2) ? fv[r].x : fv[r].y;
                        __half2 hp = *(__half2*)&hv;
                        __half2 dup = (i & 1) ? __half2half2(__high2half(hp))
                                              : __half2half2(__low2half(hp));
                        hacc[r][0] = __hfma2(dup, k0a, hacc[r][0]);
                        hacc[r][1] = __hfma2(dup, k0b, hacc[r][1]);
                        hacc[r][2] = __hfma2(dup, k1a, hacc[r][2]);
                        hacc[r][3] = __hfma2(dup, k1b, hacc[r][3]);
                    }
                }
            }
            #pragma unroll
            for (int r = 0; r < ROWS; r++) {
                #pragma unroll
                for (int k = 0; k < 4; k++) {
                    float2 t = __half22float2(hacc[r][k]);
                    dsum[r][2 * k]     += t.x;
                    dsum[r][2 * k + 1] += t.y;
                    hacc[r][k] = hz;
                }
            }
        }

        // ---------- masked softmax per row ----------
        #pragma unroll
        for (int r = 0; r < ROWS; r++) {
            float lg[8];
            float mx = -1e30f;
            #pragma unroll
            for (int s = 0; s < 8; s++) {
                unsigned wbits = (s < 4) ? aw0[r] : aw1[r];
                float b1v = (s < 4) ? comp4(b1q0, s) : comp4(b1q1, s - 4);
                bool on = (wbits >> (bsh + (s & 3))) & 1u;
                float v = on ? (dsum[r][s] + b1v) : -1e30f;
                lg[s] = v;
                mx = fmaxf(mx, v);
            }
            #pragma unroll
            for (int o = 16; o; o >>= 1) mx = fmaxf(mx, __shfl_xor_sync(0xffffffffu, mx, o));
            float ssum = 0.f;
            float ev[8];
            #pragma unroll
            for (int s = 0; s < 8; s++) {
                float e = (lg[s] > -1e29f) ? __expf(lg[s] - mx) : 0.f;
                ev[s] = e; ssum += e;
            }
            #pragma unroll
            for (int o = 16; o; o >>= 1) ssum += __shfl_xor_sync(0xffffffffu, ssum, o);
            float inv = 1.0f / ssum;
            float4 mv0 = make_float4(ev[0]*inv, ev[1]*inv, ev[2]*inv, ev[3]*inv);
            *(float4*)&mr[r * MP + j0] = mv0;
            if (j0 < 80) {
                float4 mv1 = make_float4(ev[4]*inv, ev[5]*inv, ev[6]*inv, ev[7]*inv);
                *(float4*)&mr[r * MP + 128 + j0] = mv1;
            }
        }
        __syncwarp();

        // ---------- phase 3 (sparse, fp32): node[r][f] = sum_j mask*X ----------
        float2 na[ROWS];
        #pragma unroll
        for (int r = 0; r < ROWS; r++) na[r] = make_float2(0.f, 0.f);

        #pragma unroll
        for (int r = 0; r < ROWS; r++) vbuf[0][r] = __ldg(&av[r][0]);
        #pragma unroll
        for (int r = 0; r < ROWS; r++) vbuf[1][r] = __ldg(&av[r][1]);

        #pragma unroll 2
        for (int k = 0; k < deg4; k++) {
            const int cur = k & 1;
            float2 v[ROWS];
            #pragma unroll
            for (int r = 0; r < ROWS; r++) v[r] = vbuf[cur][r];
            if (k + 2 < MAXD) {
                #pragma unroll
                for (int r = 0; r < ROWS; r++) vbuf[cur][r] = __ldg(&av[r][k + 2]);
            }
            #pragma unroll
            for (int r = 0; r < ROWS; r++) {
                int j = __float_as_int(v[r].x);
                float mval = mr[r * MP + j];
                float2 x = *(const float2*)&Xs[j * FF + f0];
                na[r].x += mval * x.x; na[r].y += mval * x.y;
            }
        }
        #pragma unroll
        for (int r = 0; r < ROWS; r++) {
            nr[r * FF + f0]     = na[r].x;
            nr[r * FF + f0 + 1] = na[r].y;
        }
        __syncwarp();

        // ---------- phase 4 (fp32): out[r][u] = sum_f node*fc + bias2 ----------
        float2 oa[ROWS];
        #pragma unroll
        for (int r = 0; r < ROWS; r++) oa[r] = make_float2(0.f, 0.f);

        #pragma unroll 2
        for (int fb = 0; fb < FF; fb += 4) {
            float4 nv[ROWS];
            #pragma unroll
            for (int r = 0; r < ROWS; r++) nv[r] = *(const float4*)&nr[r * FF + fb];
            #pragma unroll
            for (int i = 0; i < 4; i++) {
                float2 f2 = *(const float2*)&fcs[(fb + i) * UU + f0];
                #pragma unroll
                for (int r = 0; r < ROWS; r++) {
                    float nvi = comp4(nv[r], i);
                    oa[r].x += nvi * f2.x; oa[r].y += nvi * f2.y;
                }
            }
        }

        #pragma unroll
        for (int r = 0; r < ROWS; r++) {
            int m = m0 + r;
            if (m < NN) {
                size_t ob = ((size_t)b * NN + m) * OUTC + h * UU;
                out[ob + f0]     = oa[r].x + b2s[f0];
                out[ob + f0 + 1] = oa[r].y + b2s[f0 + 1];
                if (h == HH - 1) {
                    size_t mb2 = ((size_t)b * NN + m) * OUTC + HH * UU;
                    for (int j = lane; j < NN; j += 32) out[mb2 + j] = mr[r * MP + j];
                }
            }
        }
        __syncwarp();
    }
}

extern "C" void kernel_launch(void* const* d_in, const int* in_sizes, int n_in,
                              void* d_out, int out_size)
{
    const float* X       = (const float*)d_in[0];
    const float* A       = (const float*)d_in[1];
    const float* kernels = (const float*)d_in[2];
    const float* params  = (const float*)d_in[3];
    const float* fc      = (const float*)d_in[4];
    const float* bias1   = (const float*)d_in[5];
    const float* bias2   = (const float*)d_in[6];
    float* out = (float*)d_out;

    int B = in_sizes[0] / (NN * FF);

    adj_kernel<<<(HH * NN + 255) / 256, 256>>>(A, params);

    // Ksh is FF*128 half2 = FF*128 float-equivalents (4 bytes each) — 32 KB.
    const int smemFloats = NP*FF + NP*32 + FF*128 + FF*UU
                         + NWARP*ROWS*FF + NWARP*ROWS*32 + NWARP*ROWS*MP + 256 + UU;
    const int smemBytes = smemFloats * (int)sizeof(float);   // 214,784 bytes
    cudaFuncSetAttribute(gc_kernel, cudaFuncAttributeMaxDynamicSharedMemorySize, smemBytes);
    gc_kernel<<<B * HH, THREADS, smemBytes>>>(X, A, kernels, fc, bias1, bias2, out);
}

// round 9
// speedup vs baseline: 2.1765x; 1.0004x over previous
#include <cuda_runtime.h>
#include <cuda_fp16.h>
#include <math.h>

#define NN   199
#define NP   200
#define MP   208
#define FF   64
#define UU   64
#define HH   4
#define OUTC (HH*UU + NN)
#define ROWS 4
#define NWARP 18
#define THREADS (NWARP*32)
#define MAXD 96

// Compacted adjacency: for column m, entries {n, params[h][n][m]} for n with A[n][m]!=0,
// padded to MAXD with {NN, 0} (idx NN points at zeroed pad rows).
__device__ float2   g_adjv[HH * NN * MAXD];
__device__ int      g_deg[NN];
__device__ unsigned g_abits[NN * 8];

__global__ void adj_kernel(const float* __restrict__ A, const float* __restrict__ params) {
    int t = blockIdx.x * blockDim.x + threadIdx.x;
    if (t >= HH * NN) return;
    int h = t / NN, m = t - h * NN;
    float2* row = g_adjv + (size_t)t * MAXD;
    int k = 0;
    for (int n = 0; n < NN; n++) {
        if (A[n * NN + m] != 0.f) {
            if (k < MAXD) {
                float2 e;
                e.x = __int_as_float(n);
                e.y = params[((size_t)h * NN + n) * NN + m];
                row[k] = e;
            }
            k++;
        }
    }
    int deg = (k < MAXD) ? k : MAXD;
    for (int kk = deg; kk < MAXD; kk++) {
        float2 e; e.x = __int_as_float(NN); e.y = 0.f;
        row[kk] = e;
    }
    if (h == 0) {
        g_deg[m] = deg;
        unsigned wb[8] = {0,0,0,0,0,0,0,0};
        for (int j = 0; j < NN; j++)
            if (A[(size_t)m * NN + j] != 0.f) wb[j >> 5] |= (1u << (j & 31));
        for (int wd = 0; wd < 8; wd++) g_abits[m * 8 + wd] = wb[wd];
    }
}

__device__ __forceinline__ float comp4(const float4& v, int i) {
    return (i == 0) ? v.x : (i == 1) ? v.y : (i == 2) ? v.z : v.w;
}

__global__ __launch_bounds__(THREADS, 1)
void gc_kernel(const float* __restrict__ X, const float* __restrict__ A,
               const float* __restrict__ kernels, const float* __restrict__ fc,
               const float* __restrict__ bias1, const float* __restrict__ bias2,
               float* __restrict__ out)
{
    extern __shared__ float sm[];
    float*    Xs   = sm;                                    // [NP][FF] fp32 (row NN zeroed)
    unsigned* Xh2  = (unsigned*)(Xs + NP * FF);             // [NP][32] half2 (row NN zero)
    __half2*  Ksh  = (__half2*)(Xh2 + NP * 32);             // [FF][128] half2  (32 KB)
    float*    fcs  = (float*)(Ksh + FF * 128);              // [FF][UU] fp32
    float*    nbuf = fcs + FF * UU;                         // [NWARP][ROWS][FF] node fp32
    unsigned* frh  = (unsigned*)(nbuf + NWARP * ROWS * FF); // [NWARP][ROWS][32] feat half2
    float*    mrow = (float*)(frh + NWARP * ROWS * 32);     // [NWARP][ROWS][MP]
    float*    b1s  = mrow + NWARP * ROWS * MP;              // [256] (pad zero)
    float*    b2s  = b1s + 256;                             // [UU]

    const int bx   = blockIdx.x;
    const int h    = bx % HH;
    const int b    = bx / HH;
    const int tid  = threadIdx.x;
    const int lane = tid & 31;
    const int w    = tid >> 5;

    // ---------------- cooperative staging ----------------
    {
        const float* Xg = X + (size_t)b * NN * FF;
        const float4* Xg4 = (const float4*)Xg;
        float4* Xs4 = (float4*)Xs;
        #pragma unroll 1
        for (int i = tid; i < NN * FF / 4; i += THREADS) Xs4[i] = Xg4[i];
        for (int i = tid; i < FF; i += THREADS) Xs[NN * FF + i] = 0.f;

        #pragma unroll 1
        for (int i = tid; i < NP * 32; i += THREADS) {      // fp16 shadow of X
            int n = i >> 5, c = i & 31;
            float2 v = make_float2(0.f, 0.f);
            if (n < NN) v = *(const float2*)&Xg[n * FF + 2 * c];
            __half2 hv = __floats2half2_rn(v.x, v.y);
            Xh2[i] = *(unsigned*)&hv;
        }

        const float* Kg = kernels + (size_t)h * FF * NN;
        #pragma unroll 1
        for (int i = tid; i < FF * 128; i += THREADS) {     // fp16 K, [f][j] (j pairs)
            int f = i >> 7, jh = i & 127, j = 2 * jh;
            float a = (j < NN)     ? Kg[f * NN + j]     : 0.f;
            float c = (j + 1 < NN) ? Kg[f * NN + j + 1] : 0.f;
            Ksh[i] = __floats2half2_rn(a, c);
        }

        const float4* fg4 = (const float4*)(fc + (size_t)h * FF * UU);
        float4* fcs4 = (float4*)fcs;
        for (int i = tid; i < FF * UU / 4; i += THREADS) fcs4[i] = fg4[i];
        for (int i = tid; i < 256; i += THREADS) b1s[i] = (i < NN) ? bias1[h * NN + i] : 0.f;
        for (int i = tid; i < UU; i += THREADS) b2s[i] = bias2[h * UU + i];
    }
    __syncthreads();

    const int f0 = 2 * lane;
    const int j0 = 4 * lane;
    float*    nr = nbuf + (w * ROWS) * FF;
    unsigned* fw = frh  + (w * ROWS) * 32;
    float*    mr = mrow + (w * ROWS) * MP;

    const float4 b1q0 = *(const float4*)&b1s[j0];
    const float4 b1q1 = *(const float4*)&b1s[128 + j0];
    const __half2 hz = __float2half2_rn(0.f);

    for (int mb = 0; mb < NN; mb += NWARP * ROWS) {
        const int m0 = mb + w * ROWS;
        if (m0 >= NN) continue;

        int mi[ROWS];
        #pragma unroll
        for (int r = 0; r < ROWS; r++) {
            int m = m0 + r;
            mi[r] = (m < NN) ? m : (NN - 1);
        }

        const float2* av[ROWS];
        int deg4 = 0;
        #pragma unroll
        for (int r = 0; r < ROWS; r++) {
            av[r] = g_adjv + ((size_t)h * NN + mi[r]) * MAXD;
            deg4 = max(deg4, __ldg(&g_deg[mi[r]]));
        }

        // ---------- phase 1 (sparse, fp16 X, fp32 accum) ----------
        float2 fa[ROWS];
        #pragma unroll
        for (int r = 0; r < ROWS; r++) fa[r] = make_float2(0.f, 0.f);

        float2 vbuf[2][ROWS];
        #pragma unroll
        for (int r = 0; r < ROWS; r++) vbuf[0][r] = __ldg(&av[r][0]);
        #pragma unroll
        for (int r = 0; r < ROWS; r++) vbuf[1][r] = __ldg(&av[r][1]);

        #pragma unroll 2
        for (int k = 0; k < deg4; k++) {
            const int cur = k & 1;
            float2 v[ROWS];
            #pragma unroll
            for (int r = 0; r < ROWS; r++) v[r] = vbuf[cur][r];
            if (k + 2 < MAXD) {
                #pragma unroll
                for (int r = 0; r < ROWS; r++) vbuf[cur][r] = __ldg(&av[r][k + 2]);
            }
            #pragma unroll
            for (int r = 0; r < ROWS; r++) {
                int n = __float_as_int(v[r].x);
                unsigned xu = Xh2[n * 32 + lane];
                float2 xf = __half22float2(*(__half2*)&xu);
                fa[r].x += v[r].y * xf.x; fa[r].y += v[r].y * xf.y;
            }
        }
        #pragma unroll
        for (int r = 0; r < ROWS; r++) {
            __half2 hv = __floats2half2_rn(fa[r].x, fa[r].y);
            fw[r * 32 + lane] = *(unsigned*)&hv;
        }
        __syncwarp();

        // adjacency bitmask (overlaps phase 2)
        unsigned aw0[ROWS], aw1[ROWS];
        #pragma unroll
        for (int r = 0; r < ROWS; r++) {
            const unsigned* ab = g_abits + mi[r] * 8;
            aw0[r] = __ldg(&ab[lane >> 3]);
            aw1[r] = __ldg(&ab[4 + (lane >> 3)]);
        }
        const int bsh = 4 * (lane & 7);

        // ---------- phase 2 (dense, HFMA2, fp32 flush every 16 f) ----------
        float dsum[ROWS][8];
        __half2 hacc[ROWS][4];
        #pragma unroll
        for (int r = 0; r < ROWS; r++) {
            #pragma unroll
            for (int s = 0; s < 8; s++) dsum[r][s] = 0.f;
            #pragma unroll
            for (int k = 0; k < 4; k++) hacc[r][k] = hz;
        }

        #pragma unroll
        for (int chunk = 0; chunk < 4; chunk++) {
            #pragma unroll
            for (int fbq = 0; fbq < 4; fbq++) {
                const int fb = chunk * 16 + fbq * 4;
                uint2 fv[ROWS];
                #pragma unroll
                for (int r = 0; r < ROWS; r++) fv[r] = *(const uint2*)&fw[r * 32 + (fb >> 1)];
                #pragma unroll
                for (int i = 0; i < 4; i++) {
                    const __half2* kr = Ksh + (fb + i) * 128;
                    uint2 kq0 = *(const uint2*)(kr + 2 * lane);
                    uint2 kq1 = *(const uint2*)(kr + 64 + 2 * lane);
                    __half2 k0a = *(__half2*)&kq0.x, k0b = *(__half2*)&kq0.y;
                    __half2 k1a = *(__half2*)&kq1.x, k1b = *(__half2*)&kq1.y;
                    #pragma unroll
                    for (int r = 0; r < ROWS; r++) {
                        unsigned hv = (i < 2) ? fv[r].x : fv[r].y;
                        __half2 hp = *(__half2*)&hv;
                        __half2 dup = (i & 1) ? __half2half2(__high2half(hp))
                                              : __half2half2(__low2half(hp));
                        hacc[r][0] = __hfma2(dup, k0a, hacc[r][0]);
                        hacc[r][1] = __hfma2(dup, k0b, hacc[r][1]);
                        hacc[r][2] = __hfma2(dup, k1a, hacc[r][2]);
                        hacc[r][3] = __hfma2(dup, k1b, hacc[r][3]);
                    }
                }
            }
            #pragma unroll
            for (int r = 0; r < ROWS; r++) {
                #pragma unroll
                for (int k = 0; k < 4; k++) {
                    float2 t = __half22float2(hacc[r][k]);
                    dsum[r][2 * k]     += t.x;
                    dsum[r][2 * k + 1] += t.y;
                    hacc[r][k] = hz;
                }
            }
        }

        // ---------- masked softmax per row ----------
        #pragma unroll
        for (int r = 0; r < ROWS; r++) {
            float lg[8];
            float mx = -1e30f;
            #pragma unroll
            for (int s = 0; s < 8; s++) {
                unsigned wbits = (s < 4) ? aw0[r] : aw1[r];
                float b1v = (s < 4) ? comp4(b1q0, s) : comp4(b1q1, s - 4);
                bool on = (wbits >> (bsh + (s & 3))) & 1u;
                float v = on ? (dsum[r][s] + b1v) : -1e30f;
                lg[s] = v;
                mx = fmaxf(mx, v);
            }
            #pragma unroll
            for (int o = 16; o; o >>= 1) mx = fmaxf(mx, __shfl_xor_sync(0xffffffffu, mx, o));
            float ssum = 0.f;
            float ev[8];
            #pragma unroll
            for (int s = 0; s < 8; s++) {
                float e = (lg[s] > -1e29f) ? __expf(lg[s] - mx) : 0.f;
                ev[s] = e; ssum += e;
            }
            #pragma unroll
            for (int o = 16; o; o >>= 1) ssum += __shfl_xor_sync(0xffffffffu, ssum, o);
            float inv = 1.0f / ssum;
            float4 mv0 = make_float4(ev[0]*inv, ev[1]*inv, ev[2]*inv, ev[3]*inv);
            *(float4*)&mr[r * MP + j0] = mv0;
            if (j0 < 80) {
                float4 mv1 = make_float4(ev[4]*inv, ev[5]*inv, ev[6]*inv, ev[7]*inv);
                *(float4*)&mr[r * MP + 128 + j0] = mv1;
            }
        }
        __syncwarp();

        // ---------- phase 3 (sparse, fp32): node[r][f] = sum_j mask*X ----------
        float2 na[ROWS];
        #pragma unroll
        for (int r = 0; r < ROWS; r++) na[r] = make_float2(0.f, 0.f);

        #pragma unroll
        for (int r = 0; r < ROWS; r++) vbuf[0][r] = __ldg(&av[r][0]);
        #pragma unroll
        for (int r = 0; r < ROWS; r++) vbuf[1][r] = __ldg(&av[r][1]);

        #pragma unroll 2
        for (int k = 0; k < deg4; k++) {
            const int cur = k & 1;
            float2 v[ROWS];
            #pragma unroll
            for (int r = 0; r < ROWS; r++) v[r] = vbuf[cur][r];
            if (k + 2 < MAXD) {
                #pragma unroll
                for (int r = 0; r < ROWS; r++) vbuf[cur][r] = __ldg(&av[r][k + 2]);
            }
            #pragma unroll
            for (int r = 0; r < ROWS; r++) {
                int j = __float_as_int(v[r].x);
                float mval = mr[r * MP + j];
                float2 x = *(const float2*)&Xs[j * FF + f0];
                na[r].x += mval * x.x; na[r].y += mval * x.y;
            }
        }
        #pragma unroll
        for (int r = 0; r < ROWS; r++) {
            nr[r * FF + f0]     = na[r].x;
            nr[r * FF + f0 + 1] = na[r].y;
        }
        __syncwarp();

        // ---------- phase 4 (fp32): out[r][u] = sum_f node*fc + bias2 ----------
        float2 oa[ROWS];
        #pragma unroll
        for (int r = 0; r < ROWS; r++) oa[r] = make_float2(0.f, 0.f);

        #pragma unroll 2
        for (int fb = 0; fb < FF; fb += 4) {
            float4 nv[ROWS];
            #pragma unroll
            for (int r = 0; r < ROWS; r++) nv[r] = *(const float4*)&nr[r * FF + fb];
            #pragma unroll
            for (int i = 0; i < 4; i++) {
                float2 f2 = *(const float2*)&fcs[(fb + i) * UU + f0];
                #pragma unroll
                for (int r = 0; r < ROWS; r++) {
                    float nvi = comp4(nv[r], i);
                    oa[r].x += nvi * f2.x; oa[r].y += nvi * f2.y;
                }
            }
        }

        #pragma unroll
        for (int r = 0; r < ROWS; r++) {
            int m = m0 + r;
            if (m < NN) {
                size_t ob = ((size_t)b * NN + m) * OUTC + h * UU;
                out[ob + f0]     = oa[r].x + b2s[f0];
                out[ob + f0 + 1] = oa[r].y + b2s[f0 + 1];
                if (h == HH - 1) {
                    size_t mb2 = ((size_t)b * NN + m) * OUTC + HH * UU;
                    for (int j = lane; j < NN; j += 32) out[mb2 + j] = mr[r * MP + j];
                }
            }
        }
        __syncwarp();
    }
}

extern "C" void kernel_launch(void* const* d_in, const int* in_sizes, int n_in,
                              void* d_out, int out_size)
{
    const float* X       = (const float*)d_in[0];
    const float* A       = (const float*)d_in[1];
    const float* kernels = (const float*)d_in[2];
    const float* params  = (const float*)d_in[3];
    const float* fc      = (const float*)d_in[4];
    const float* bias1   = (const float*)d_in[5];
    const float* bias2   = (const float*)d_in[6];
    float* out = (float*)d_out;

    int B = in_sizes[0] / (NN * FF);

    adj_kernel<<<(HH * NN + 255) / 256, 256>>>(A, params);

    // Ksh is FF*128 half2 = FF*128 float-equivalents (4 bytes each) — 32 KB.
    const int smemFloats = NP*FF + NP*32 + FF*128 + FF*UU
                         + NWARP*ROWS*FF + NWARP*ROWS*32 + NWARP*ROWS*MP + 256 + UU;
    const int smemBytes = smemFloats * (int)sizeof(float);   // 214,784 bytes
    cudaFuncSetAttribute(gc_kernel, cudaFuncAttributeMaxDynamicSharedMemorySize, smemBytes);
    gc_kernel<<<B * HH, THREADS, smemBytes>>>(X, A, kernels, fc, bias1, bias2, out);
}

// round 12
// speedup vs baseline: 7.3666x; 3.3846x over previous
#include <cuda_runtime.h>
#include <cuda_fp16.h>
#include <cstdint>

#define NN 199
#define FF 64
#define HH 4
#define MR 208
#define NJ 216
#define SF 72
#define OUTC 455
#define NW 13
#define THREADS (NW*32)

__device__ __align__(16) __half g_AWT[HH*MR*NJ];
__device__ __align__(16) __half g_MAD[HH*MR*NJ];
__device__ __align__(16) __half g_KT [HH*MR*SF];
__device__ __align__(16) __half g_FCC[HH*2*FF*SF];
__device__ __align__(16) __half g_XT [512u*FF*NJ];

__global__ void prep_const(const float* __restrict__ A, const float* __restrict__ P,
                           const float* __restrict__ K, const float* __restrict__ FC,
                           const float* __restrict__ B1) {
    int i = blockIdx.x*blockDim.x + threadIdx.x;
    const int T1 = HH*MR*NJ;
    if (i < T1) {
        int n = i%NJ, m = (i/NJ)%MR, h = i/(NJ*MR);
        float v = 0.f, wv = -1e30f;
        if (m < NN && n < NN) {
            float a = A[n*NN+m];
            if (a != 0.f) v = a * P[((size_t)h*NN+n)*NN+m];
            if (A[m*NN+n] != 0.f) wv = B1[h*NN+n];
        }
        g_AWT[i] = __float2half_rn(v);
        g_MAD[i] = __float2half_rn(wv);
        return;
    }
    i -= T1;
    const int T2 = HH*MR*SF;
    if (i < T2) {
        int f = i%SF, j = (i/SF)%MR, h = i/(SF*MR);
        g_KT[i] = __float2half_rn((f < FF && j < NN) ? K[((size_t)h*FF+f)*NN+j] : 0.f);
        return;
    }
    i -= T2;
    if (i < HH*2*FF*SF) {
        int f = i%SF, u = (i/SF)%FF, p = (i/(SF*FF))&1, h = i/(SF*FF*2);
        float x = (f < FF) ? FC[((size_t)h*FF+f)*FF+u] : 0.f;
        __half hi = __float2half_rn(x);
        g_FCC[i] = p ? __float2half_rn(x - __half2float(hi)) : hi;
    }
}

__global__ void prep_x(const float* __restrict__ X) {
    __shared__ float xs[NN*FF];
    int b = blockIdx.x;
    const float* xb = X + (size_t)b*NN*FF;
    for (int i = threadIdx.x; i < NN*FF; i += blockDim.x) xs[i] = xb[i];
    __syncthreads();
    __half* d = g_XT + (size_t)b*FF*NJ;
    for (int i = threadIdx.x; i < FF*NJ; i += blockDim.x) {
        int n = i%NJ, f = i/NJ;
        d[i] = __float2half_rn(n < NN ? xs[n*FF+f] : 0.f);
    }
}

__device__ __forceinline__ uint32_t s2u(const void* p) {
    uint32_t a; asm("{.reg .u64 t; cvta.to.shared.u64 t,%1; cvt.u32.u64 %0,t;}" : "=r"(a) : "l"(p)); return a;
}
#define LDM4(r0,r1,r2,r3,ad) asm volatile("ldmatrix.sync.aligned.m8n8.x4.shared.b16 {%0,%1,%2,%3},[%4];":"=r"(r0),"=r"(r1),"=r"(r2),"=r"(r3):"r"(ad))
#define LDM2(r0,r1,ad) asm volatile("ldmatrix.sync.aligned.m8n8.x2.shared.b16 {%0,%1},[%2];":"=r"(r0),"=r"(r1):"r"(ad))
#define MMA16(c,a0,a1,a2,a3,b0,b1) asm volatile("mma.sync.aligned.m16n8k16.row.col.f32.f16.f16.f32 {%0,%1,%2,%3},{%4,%5,%6,%7},{%8,%9},{%0,%1,%2,%3};":"+f"(c[0]),"+f"(c[1]),"+f"(c[2]),"+f"(c[3]):"r"(a0),"r"(a1),"r"(a2),"r"(a3),"r"(b0),"r"(b1))
#define ADRA(u,S,k0) ((u) + (((lane&15)*(S) + (k0) + ((lane>>4)<<3))<<1))
#define ADRB(u,S,r0,k0) ((u) + ((((r0)+(lane&7))*(S) + (k0) + (((lane>>3)&1)<<3))<<1))

__global__ __launch_bounds__(THREADS, 1)
void gc_kernel(const float* __restrict__ bias2, float* __restrict__ out) {
    extern __shared__ __half sh[];
    __half* sXt = sh;              // [FF][NJ]
    __half* sKt = sXt + FF*NJ;     // [MR][SF]
    __half* sFH = sKt + MR*SF;     // [FF][SF]
    __half* sFL = sFH + FF*SF;
    __half* swk = sFL + FF*SF;     // per-warp: mask 16*NJ + ft 16*SF + nl 16*SF

    const int bx = blockIdx.x, h = bx & 3, b = bx >> 2;
    const int tid = threadIdx.x, lane = tid & 31, w = tid >> 5;
    const int g = lane >> 2, t = lane & 3;

    {   // stage block-wide fp16 operands (16B copies)
        const uint4* s1 = (const uint4*)(g_XT + (size_t)b*FF*NJ); uint4* d1 = (uint4*)sXt;
        for (int i = tid; i < FF*NJ/8; i += THREADS) d1[i] = s1[i];
        const uint4* s2 = (const uint4*)(g_KT + (size_t)h*MR*SF); uint4* d2 = (uint4*)sKt;
        for (int i = tid; i < MR*SF/8; i += THREADS) d2[i] = s2[i];
        const uint4* s3 = (const uint4*)(g_FCC + (size_t)(h*2)*FF*SF); uint4* d3 = (uint4*)sFH;
        for (int i = tid; i < 2*FF*SF/8; i += THREADS) d3[i] = s3[i];
    }
    __syncthreads();

    __half* mk = swk + w*(16*NJ + 32*SF);
    __half* ft = mk + 16*NJ;
    __half* nl = ft + 16*SF;
    const uint32_t uXt = s2u(sXt), uKt = s2u(sKt), uFH = s2u(sFH), uFL = s2u(sFL);
    const uint32_t uMk = s2u(mk), uFt = s2u(ft), uNl = s2u(nl);
    const int m0 = w*16;
    const int mA = m0 + g, mB = m0 + g + 8;

    // ---- phase 1: feat = AWT x Xt^T  (A frags direct from global, L2-hot) ----
    {
        float c[8][4] = {};
        const __half* aw = g_AWT + ((size_t)h*MR + m0)*NJ;
        #pragma unroll
        for (int ks = 0; ks < 13; ks++) {
            const __half* pk = aw + 16*ks + 2*t;
            uint32_t a0 = *(const uint32_t*)(pk + g*NJ);
            uint32_t a1 = *(const uint32_t*)(pk + (g+8)*NJ);
            uint32_t a2 = *(const uint32_t*)(pk + g*NJ + 8);
            uint32_t a3 = *(const uint32_t*)(pk + (g+8)*NJ + 8);
            #pragma unroll
            for (int nt = 0; nt < 8; nt++) {
                uint32_t b0, b1; LDM2(b0, b1, ADRB(uXt, NJ, 8*nt, 16*ks));
                MMA16(c[nt], a0, a1, a2, a3, b0, b1);
            }
        }
        #pragma unroll
        for (int nt = 0; nt < 8; nt++) {
            int fc0 = 8*nt + 2*t;
            *(__half2*)(ft + g*SF + fc0)     = __floats2half2_rn(c[nt][0], c[nt][1]);
            *(__half2*)(ft + (g+8)*SF + fc0) = __floats2half2_rn(c[nt][2], c[nt][3]);
        }
    }
    __syncwarp();

    // ---- phase 2: dense = feat x Kt^T, + MAD(bias1 / -inf) ----
    float d[26][4] = {};
    #pragma unroll
    for (int ks = 0; ks < 4; ks++) {
        uint32_t a0, a1, a2, a3; LDM4(a0, a1, a2, a3, ADRA(uFt, SF, 16*ks));
        #pragma unroll
        for (int nt = 0; nt < 26; nt++) {
            uint32_t b0, b1; LDM2(b0, b1, ADRB(uKt, SF, 8*nt, 16*ks));
            MMA16(d[nt], a0, a1, a2, a3, b0, b1);
        }
    }
    {   // masked softmax on frags (rows mA, mB per lane-quad)
        const __half* md = g_MAD + ((size_t)h*MR + m0)*NJ + 2*t;
        float mxA = -3e38f, mxB = -3e38f;
        #pragma unroll
        for (int nt = 0; nt < 26; nt++) {
            __half2 u0 = *(const __half2*)(md + g*NJ + 8*nt);
            __half2 u1 = *(const __half2*)(md + (g+8)*NJ + 8*nt);
            float2 f0 = __half22float2(u0), f1 = __half22float2(u1);
            d[nt][0] += f0.x; d[nt][1] += f0.y; d[nt][2] += f1.x; d[nt][3] += f1.y;
            mxA = fmaxf(mxA, fmaxf(d[nt][0], d[nt][1]));
            mxB = fmaxf(mxB, fmaxf(d[nt][2], d[nt][3]));
        }
        mxA = fmaxf(mxA, __shfl_xor_sync(~0u, mxA, 1)); mxA = fmaxf(mxA, __shfl_xor_sync(~0u, mxA, 2));
        mxB = fmaxf(mxB, __shfl_xor_sync(~0u, mxB, 1)); mxB = fmaxf(mxB, __shfl_xor_sync(~0u, mxB, 2));
        float sA = 0.f, sB = 0.f;
        #pragma unroll
        for (int nt = 0; nt < 26; nt++) {
            d[nt][0] = __expf(d[nt][0] - mxA); d[nt][1] = __expf(d[nt][1] - mxA);
            d[nt][2] = __expf(d[nt][2] - mxB); d[nt][3] = __expf(d[nt][3] - mxB);
            sA += d[nt][0] + d[nt][1]; sB += d[nt][2] + d[nt][3];
        }
        sA += __shfl_xor_sync(~0u, sA, 1); sA += __shfl_xor_sync(~0u, sA, 2);
        sB += __shfl_xor_sync(~0u, sB, 1); sB += __shfl_xor_sync(~0u, sB, 2);
        float iA = 1.f/sA, iB = 1.f/sB;
        const bool wm = (h == 3);
        size_t oA = ((size_t)b*NN + mA)*OUTC + 256, oB = ((size_t)b*NN + mB)*OUTC + 256;
        #pragma unroll
        for (int nt = 0; nt < 26; nt++) {
            int j = 8*nt + 2*t;
            float v0 = d[nt][0]*iA, v1 = d[nt][1]*iA, v2 = d[nt][2]*iB, v3 = d[nt][3]*iB;
            *(__half2*)(mk + g*NJ + j)     = __floats2half2_rn(v0, v1);
            *(__half2*)(mk + (g+8)*NJ + j) = __floats2half2_rn(v2, v3);
            if (wm) {
                if (mA < NN) { if (j < NN) out[oA+j] = v0; if (j+1 < NN) out[oA+j+1] = v1; }
                if (mB < NN) { if (j < NN) out[oB+j] = v2; if (j+1 < NN) out[oB+j+1] = v3; }
            }
        }
    }
    __syncwarp();

    // ---- phase 4: node = mask x Xt^T ----
    {
        float c[8][4] = {};
        #pragma unroll
        for (int ks = 0; ks < 13; ks++) {
            uint32_t a0, a1, a2, a3; LDM4(a0, a1, a2, a3, ADRA(uMk, NJ, 16*ks));
            #pragma unroll
            for (int nt = 0; nt < 8; nt++) {
                uint32_t b0, b1; LDM2(b0, b1, ADRB(uXt, NJ, 8*nt, 16*ks));
                MMA16(c[nt], a0, a1, a2, a3, b0, b1);
            }
        }
        __syncwarp();
        #pragma unroll
        for (int nt = 0; nt < 8; nt++) {
            int fc0 = 8*nt + 2*t;
            __half h0 = __float2half_rn(c[nt][0]), h1 = __float2half_rn(c[nt][1]);
            __half h2 = __float2half_rn(c[nt][2]), h3 = __float2half_rn(c[nt][3]);
            *(__half2*)(ft + g*SF + fc0)     = __halves2half2(h0, h1);
            *(__half2*)(ft + (g+8)*SF + fc0) = __halves2half2(h2, h3);
            *(__half2*)(nl + g*SF + fc0)     = __floats2half2_rn(c[nt][0]-__half2float(h0), c[nt][1]-__half2float(h1));
            *(__half2*)(nl + (g+8)*SF + fc0) = __floats2half2_rn(c[nt][2]-__half2float(h2), c[nt][3]-__half2float(h3));
        }
    }
    __syncwarp();

    // ---- phase 5: out = nodeH*fcH + nodeL*fcH + nodeH*fcL + bias2 ----
    {
        float c[8][4] = {};
        #pragma unroll
        for (int ks = 0; ks < 4; ks++) {
            uint32_t aH0, aH1, aH2, aH3, aL0, aL1, aL2, aL3;
            LDM4(aH0, aH1, aH2, aH3, ADRA(uFt, SF, 16*ks));
            LDM4(aL0, aL1, aL2, aL3, ADRA(uNl, SF, 16*ks));
            #pragma unroll
            for (int nt = 0; nt < 8; nt++) {
                uint32_t bH0, bH1, bL0, bL1;
                LDM2(bH0, bH1, ADRB(uFH, SF, 8*nt, 16*ks));
                LDM2(bL0, bL1, ADRB(uFL, SF, 8*nt, 16*ks));
                MMA16(c[nt], aH0, aH1, aH2, aH3, bH0, bH1);
                MMA16(c[nt], aL0, aL1, aL2, aL3, bH0, bH1);
                MMA16(c[nt], aH0, aH1, aH2, aH3, bL0, bL1);
            }
        }
        size_t oA = ((size_t)b*NN + mA)*OUTC + h*64, oB = ((size_t)b*NN + mB)*OUTC + h*64;
        #pragma unroll
        for (int nt = 0; nt < 8; nt++) {
            int u = 8*nt + 2*t;
            float2 b2 = *(const float2*)&bias2[h*64 + u];
            if (mA < NN) {                 // OUTC is odd: scalar stores (float2 misaligns)
                out[oA+u]   = c[nt][0] + b2.x;
                out[oA+u+1] = c[nt][1] + b2.y;
            }
            if (mB < NN) {
                out[oB+u]   = c[nt][2] + b2.x;
                out[oB+u+1] = c[nt][3] + b2.y;
            }
        }
    }
}

extern "C" void kernel_launch(void* const* d_in, const int* in_sizes, int n_in,
                              void* d_out, int out_size)
{
    const float* X  = (const float*)d_in[0];
    const float* A  = (const float*)d_in[1];
    const float* Kn = (const float*)d_in[2];
    const float* P  = (const float*)d_in[3];
    const float* FC = (const float*)d_in[4];
    const float* B1 = (const float*)d_in[5];
    const float* B2 = (const float*)d_in[6];
    float* out = (float*)d_out;

    int B = in_sizes[0] / (NN*FF);

    int tot = HH*MR*NJ + HH*MR*SF + HH*2*FF*SF;
    prep_const<<<(tot + 255)/256, 256>>>(A, P, Kn, FC, B1);
    prep_x<<<B, 256>>>(X);

    const int smemBytes = (FF*NJ + MR*SF + 2*FF*SF + NW*(16*NJ + 32*SF)) * 2;  // 225,792
    cudaFuncSetAttribute(gc_kernel, cudaFuncAttributeMaxDynamicSharedMemorySize, smemBytes);
    gc_kernel<<<B*HH, THREADS, smemBytes>>>(B2, out);
}

// round 15
// speedup vs baseline: 8.4333x; 1.1448x over previous
#include <cuda_runtime.h>
#include <cuda_fp16.h>
#include <cstdint>

#define NN 199
#define FF 64
#define HH 4
#define MR 208
#define NJ 216
#define SF 72
#define OUTC 455
#define NW 13
#define THREADS (NW*32)

__device__ __align__(16) __half g_AWT[HH*MR*NJ];
__device__ __align__(16) __half g_MAD[HH*MR*NJ];
__device__ __align__(16) __half g_KT [HH*MR*SF];
__device__ __align__(16) __half g_FCC[HH*2*FF*SF];
__device__ __align__(16) __half g_XT [512u*FF*NJ];

__global__ void prep_const(const float* __restrict__ A, const float* __restrict__ P,
                           const float* __restrict__ K, const float* __restrict__ FC,
                           const float* __restrict__ B1) {
    int i = blockIdx.x*blockDim.x + threadIdx.x;
    const int T1 = HH*MR*NJ;
    if (i < T1) {
        int n = i%NJ, m = (i/NJ)%MR, h = i/(NJ*MR);
        float v = 0.f, wv = -1e30f;
        if (m < NN && n < NN) {
            float a = A[n*NN+m];
            if (a != 0.f) v = a * P[((size_t)h*NN+n)*NN+m];
            if (A[m*NN+n] != 0.f) wv = B1[h*NN+n];
        }
        g_AWT[i] = __float2half_rn(v);
        g_MAD[i] = __float2half_rn(wv);
        return;
    }
    i -= T1;
    const int T2 = HH*MR*SF;
    if (i < T2) {
        int f = i%SF, j = (i/SF)%MR, h = i/(SF*MR);
        g_KT[i] = __float2half_rn((f < FF && j < NN) ? K[((size_t)h*FF+f)*NN+j] : 0.f);
        return;
    }
    i -= T2;
    if (i < HH*2*FF*SF) {
        int f = i%SF, u = (i/SF)%FF, p = (i/(SF*FF))&1, h = i/(SF*FF*2);
        float x = (f < FF) ? FC[((size_t)h*FF+f)*FF+u] : 0.f;
        __half hi = __float2half_rn(x);
        g_FCC[i] = p ? __float2half_rn(x - __half2float(hi)) : hi;
    }
}

__global__ void prep_x(const float* __restrict__ X) {
    __shared__ float xs[NN*FF];
    int b = blockIdx.x;
    const float* xb = X + (size_t)b*NN*FF;
    for (int i = threadIdx.x; i < NN*FF; i += blockDim.x) xs[i] = xb[i];
    __syncthreads();
    __half* d = g_XT + (size_t)b*FF*NJ;
    for (int i = threadIdx.x; i < FF*NJ; i += blockDim.x) {
        int n = i%NJ, f = i/NJ;
        d[i] = __float2half_rn(n < NN ? xs[n*FF+f] : 0.f);
    }
}

__device__ __forceinline__ uint32_t s2u(const void* p) {
    uint32_t a; asm("{.reg .u64 t; cvta.to.shared.u64 t,%1; cvt.u32.u64 %0,t;}" : "=r"(a) : "l"(p)); return a;
}
__device__ __forceinline__ uint32_t packh2(float x, float y) {
    __half2 hv = __floats2half2_rn(x, y);
    return *(uint32_t*)&hv;
}
#define LDM2(r0,r1,ad) asm volatile("ldmatrix.sync.aligned.m8n8.x2.shared.b16 {%0,%1},[%2];":"=r"(r0),"=r"(r1):"r"(ad))
#define MMA16(c,a0,a1,a2,a3,b0,b1) asm volatile("mma.sync.aligned.m16n8k16.row.col.f32.f16.f16.f32 {%0,%1,%2,%3},{%4,%5,%6,%7},{%8,%9},{%0,%1,%2,%3};":"+f"(c[0]),"+f"(c[1]),"+f"(c[2]),"+f"(c[3]):"r"(a0),"r"(a1),"r"(a2),"r"(a3),"r"(b0),"r"(b1))
#define ADRB(u,S,r0,k0) ((u) + ((((r0)+(lane&7))*(S) + (k0) + (((lane>>3)&1)<<3))<<1))

__global__ __launch_bounds__(THREADS, 1)
void gc_kernel(const float* __restrict__ bias2, float* __restrict__ out) {
    extern __shared__ __half sh[];
    __half* sXt = sh;              // [FF][NJ]
    __half* sKt = sXt + FF*NJ;     // [MR][SF]
    __half* sFH = sKt + MR*SF;     // [FF][SF]
    __half* sFL = sFH + FF*SF;

    const int bx = blockIdx.x, h = bx & 3, b = bx >> 2;
    const int tid = threadIdx.x, lane = tid & 31, w = tid >> 5;
    const int g = lane >> 2, t = lane & 3;

    {   // stage block-wide fp16 operands (16B copies)
        const uint4* s1 = (const uint4*)(g_XT + (size_t)b*FF*NJ); uint4* d1 = (uint4*)sXt;
        for (int i = tid; i < FF*NJ/8; i += THREADS) d1[i] = s1[i];
        const uint4* s2 = (const uint4*)(g_KT + (size_t)h*MR*SF); uint4* d2 = (uint4*)sKt;
        for (int i = tid; i < MR*SF/8; i += THREADS) d2[i] = s2[i];
        const uint4* s3 = (const uint4*)(g_FCC + (size_t)(h*2)*FF*SF); uint4* d3 = (uint4*)sFH;
        for (int i = tid; i < 2*FF*SF/8; i += THREADS) d3[i] = s3[i];
    }
    __syncthreads();

    const uint32_t uXt = s2u(sXt), uKt = s2u(sKt), uFH = s2u(sFH), uFL = s2u(sFL);
    const int m0 = w*16;
    const int mA = m0 + g, mB = m0 + g + 8;

    // ---- phase 1: feat = AWT x Xt^T (A frags from global, C stays in regs) ----
    uint32_t aF[4][4];
    {
        float c[8][4] = {};
        const __half* aw = g_AWT + ((size_t)h*MR + m0)*NJ;
        #pragma unroll
        for (int ks = 0; ks < 13; ks++) {
            const __half* pk = aw + 16*ks + 2*t;
            uint32_t a0 = *(const uint32_t*)(pk + g*NJ);
            uint32_t a1 = *(const uint32_t*)(pk + (g+8)*NJ);
            uint32_t a2 = *(const uint32_t*)(pk + g*NJ + 8);
            uint32_t a3 = *(const uint32_t*)(pk + (g+8)*NJ + 8);
            #pragma unroll
            for (int nt = 0; nt < 8; nt++) {
                uint32_t b0, b1; LDM2(b0, b1, ADRB(uXt, NJ, 8*nt, 16*ks));
                MMA16(c[nt], a0, a1, a2, a3, b0, b1);
            }
        }
        #pragma unroll
        for (int ks = 0; ks < 4; ks++) {    // C frag -> A frag of phase 2 (k = f axis)
            aF[ks][0] = packh2(c[2*ks][0],   c[2*ks][1]);
            aF[ks][1] = packh2(c[2*ks][2],   c[2*ks][3]);
            aF[ks][2] = packh2(c[2*ks+1][0], c[2*ks+1][1]);
            aF[ks][3] = packh2(c[2*ks+1][2], c[2*ks+1][3]);
        }
    }

    // ---- phase 2: dense = feat x Kt^T; accumulators pre-loaded with bias1/-inf ----
    float d[26][4];
    {
        const __half* md = g_MAD + ((size_t)h*MR + m0)*NJ + 2*t;
        #pragma unroll
        for (int nt = 0; nt < 26; nt++) {
            __half2 u0 = *(const __half2*)(md + g*NJ + 8*nt);
            __half2 u1 = *(const __half2*)(md + (g+8)*NJ + 8*nt);
            float2 f0 = __half22float2(u0), f1 = __half22float2(u1);
            d[nt][0] = f0.x; d[nt][1] = f0.y; d[nt][2] = f1.x; d[nt][3] = f1.y;
        }
        #pragma unroll
        for (int ks = 0; ks < 4; ks++) {
            #pragma unroll
            for (int nt = 0; nt < 26; nt++) {
                uint32_t b0, b1; LDM2(b0, b1, ADRB(uKt, SF, 8*nt, 16*ks));
                MMA16(d[nt], aF[ks][0], aF[ks][1], aF[ks][2], aF[ks][3], b0, b1);
            }
        }
    }

    // ---- softmax on frags; normalized mask packed directly into A frags ----
    uint32_t aM[13][4];
    {
        float mxA = -3e38f, mxB = -3e38f;
        #pragma unroll
        for (int nt = 0; nt < 26; nt++) {
            mxA = fmaxf(mxA, fmaxf(d[nt][0], d[nt][1]));
            mxB = fmaxf(mxB, fmaxf(d[nt][2], d[nt][3]));
        }
        mxA = fmaxf(mxA, __shfl_xor_sync(~0u, mxA, 1)); mxA = fmaxf(mxA, __shfl_xor_sync(~0u, mxA, 2));
        mxB = fmaxf(mxB, __shfl_xor_sync(~0u, mxB, 1)); mxB = fmaxf(mxB, __shfl_xor_sync(~0u, mxB, 2));
        float sA = 0.f, sB = 0.f;
        #pragma unroll
        for (int nt = 0; nt < 26; nt++) {
            d[nt][0] = __expf(d[nt][0] - mxA); d[nt][1] = __expf(d[nt][1] - mxA);
            d[nt][2] = __expf(d[nt][2] - mxB); d[nt][3] = __expf(d[nt][3] - mxB);
            sA += d[nt][0] + d[nt][1]; sB += d[nt][2] + d[nt][3];
        }
        sA += __shfl_xor_sync(~0u, sA, 1); sA += __shfl_xor_sync(~0u, sA, 2);
        sB += __shfl_xor_sync(~0u, sB, 1); sB += __shfl_xor_sync(~0u, sB, 2);
        float iA = 1.f/sA, iB = 1.f/sB;
        const bool wm = (h == 3);
        size_t oA = ((size_t)b*NN + mA)*OUTC + 256, oB = ((size_t)b*NN + mB)*OUTC + 256;
        #pragma unroll
        for (int nt = 0; nt < 26; nt++) {
            float v0 = d[nt][0]*iA, v1 = d[nt][1]*iA, v2 = d[nt][2]*iB, v3 = d[nt][3]*iB;
            aM[nt>>1][(nt&1)*2 + 0] = packh2(v0, v1);
            aM[nt>>1][(nt&1)*2 + 1] = packh2(v2, v3);
            if (wm) {
                int j = 8*nt + 2*t;
                if (mA < NN) { if (j < NN) out[oA+j] = v0; if (j+1 < NN) out[oA+j+1] = v1; }
                if (mB < NN) { if (j < NN) out[oB+j] = v2; if (j+1 < NN) out[oB+j+1] = v3; }
            }
        }
    }

    // ---- phase 4: node = mask x Xt^T (A frags direct from registers) ----
    uint32_t aH[4][4], aL[4][4];
    {
        float c[8][4] = {};
        #pragma unroll
        for (int ks = 0; ks < 13; ks++) {
            #pragma unroll
            for (int nt = 0; nt < 8; nt++) {
                uint32_t b0, b1; LDM2(b0, b1, ADRB(uXt, NJ, 8*nt, 16*ks));
                MMA16(c[nt], aM[ks][0], aM[ks][1], aM[ks][2], aM[ks][3], b0, b1);
            }
        }
        #pragma unroll
        for (int ks = 0; ks < 4; ks++) {    // node hi/lo split, packed as phase-5 A frags
            #pragma unroll
            for (int q = 0; q < 4; q++) {
                int nt = 2*ks + (q >> 1);
                float x = c[nt][(q&1)*2], y = c[nt][(q&1)*2+1];
                __half hx = __float2half_rn(x), hy = __float2half_rn(y);
                __half2 hv = __halves2half2(hx, hy);
                aH[ks][q] = *(uint32_t*)&hv;
                __half2 lv = __floats2half2_rn(x - __half2float(hx), y - __half2float(hy));
                aL[ks][q] = *(uint32_t*)&lv;
            }
        }
    }

    // ---- phase 5: out = nodeH*fcH + nodeL*fcH + nodeH*fcL + bias2 ----
    {
        float c[8][4] = {};
        #pragma unroll
        for (int ks = 0; ks < 4; ks++) {
            #pragma unroll
            for (int nt = 0; nt < 8; nt++) {
                uint32_t bH0, bH1, bL0, bL1;
                LDM2(bH0, bH1, ADRB(uFH, SF, 8*nt, 16*ks));
                LDM2(bL0, bL1, ADRB(uFL, SF, 8*nt, 16*ks));
                MMA16(c[nt], aH[ks][0], aH[ks][1], aH[ks][2], aH[ks][3], bH0, bH1);
                MMA16(c[nt], aL[ks][0], aL[ks][1], aL[ks][2], aL[ks][3], bH0, bH1);
                MMA16(c[nt], aH[ks][0], aH[ks][1], aH[ks][2], aH[ks][3], bL0, bL1);
            }
        }
        size_t oA = ((size_t)b*NN + mA)*OUTC + h*64, oB = ((size_t)b*NN + mB)*OUTC + h*64;
        #pragma unroll
        for (int nt = 0; nt < 8; nt++) {
            int u = 8*nt + 2*t;
            float2 b2 = *(const float2*)&bias2[h*64 + u];
            if (mA < NN) {                 // OUTC odd: scalar stores
                out[oA+u]   = c[nt][0] + b2.x;
                out[oA+u+1] = c[nt][1] + b2.y;
            }
            if (mB < NN) {
                out[oB+u]   = c[nt][2] + b2.x;
                out[oB+u+1] = c[nt][3] + b2.y;
            }
        }
    }
}

extern "C" void kernel_launch(void* const* d_in, const int* in_sizes, int n_in,
                              void* d_out, int out_size)
{
    const float* X  = (const float*)d_in[0];
    const float* A  = (const float*)d_in[1];
    const float* Kn = (const float*)d_in[2];
    const float* P  = (const float*)d_in[3];
    const float* FC = (const float*)d_in[4];
    const float* B1 = (const float*)d_in[5];
    const float* B2 = (const float*)d_in[6];
    float* out = (float*)d_out;

    int B = in_sizes[0] / (NN*FF);

    int tot = HH*MR*NJ + HH*MR*SF + HH*2*FF*SF;
    prep_const<<<(tot + 255)/256, 256>>>(A, P, Kn, FC, B1);
    prep_x<<<B, 256>>>(X);

    const int smemBytes = (FF*NJ + MR*SF + 2*FF*SF) * 2;   // 76,032 B
    cudaFuncSetAttribute(gc_kernel, cudaFuncAttributeMaxDynamicSharedMemorySize, smemBytes);
    gc_kernel<<<B*HH, THREADS, smemBytes>>>(B2, out);
}

// round 16
// speedup vs baseline: 9.2594x; 1.0980x over previous
#include <cuda_runtime.h>
#include <cuda_fp16.h>
#include <cstdint>

#define NN 199
#define FF 64
#define HH 4
#define MR 224
#define NJ 216
#define SF 72
#define OUTC 455
#define NWB 7            // warps per block (2 blocks per (b,h))
#define THREADS (NWB*32)
#define NT2 25           // phase-2 j tiles (200 cols >= 199)

__device__ __align__(16) __half g_AWT[HH*MR*NJ];
__device__ __align__(16) __half g_MAD[HH*MR*NJ];
__device__ __align__(16) __half g_KT [HH*MR*SF];
__device__ __align__(16) __half g_FCC[HH*2*FF*SF];
__device__ __align__(16) __half g_XT [512u*FF*NJ];

__global__ void prep_const(const float* __restrict__ A, const float* __restrict__ P,
                           const float* __restrict__ K, const float* __restrict__ FC,
                           const float* __restrict__ B1) {
    int i = blockIdx.x*blockDim.x + threadIdx.x;
    const int T1 = HH*MR*NJ;
    if (i < T1) {
        int n = i%NJ, m = (i/NJ)%MR, h = i/(NJ*MR);
        float v = 0.f, wv = -1e30f;
        if (m < NN && n < NN) {
            float a = A[n*NN+m];
            if (a != 0.f) v = a * P[((size_t)h*NN+n)*NN+m];
            if (A[m*NN+n] != 0.f) wv = B1[h*NN+n];
        }
        g_AWT[i] = __float2half_rn(v);
        g_MAD[i] = __float2half_rn(wv);
        return;
    }
    i -= T1;
    const int T2 = HH*MR*SF;
    if (i < T2) {
        int f = i%SF, j = (i/SF)%MR, h = i/(SF*MR);
        g_KT[i] = __float2half_rn((f < FF && j < NN) ? K[((size_t)h*FF+f)*NN+j] : 0.f);
        return;
    }
    i -= T2;
    if (i < HH*2*FF*SF) {
        int f = i%SF, u = (i/SF)%FF, p = (i/(SF*FF))&1, h = i/(SF*FF*2);
        float x = (f < FF) ? FC[((size_t)h*FF+f)*FF+u] : 0.f;
        __half hi = __float2half_rn(x);
        g_FCC[i] = p ? __float2half_rn(x - __half2float(hi)) : hi;
    }
}

__global__ void prep_x(const float* __restrict__ X) {
    __shared__ float xs[NN*FF];
    int b = blockIdx.x;
    const float* xb = X + (size_t)b*NN*FF;
    for (int i = threadIdx.x; i < NN*FF; i += blockDim.x) xs[i] = xb[i];
    __syncthreads();
    __half* d = g_XT + (size_t)b*FF*NJ;
    for (int i = threadIdx.x; i < FF*NJ; i += blockDim.x) {
        int n = i%NJ, f = i/NJ;
        d[i] = __float2half_rn(n < NN ? xs[n*FF+f] : 0.f);
    }
}

__device__ __forceinline__ uint32_t s2u(const void* p) {
    uint32_t a; asm("{.reg .u64 t; cvta.to.shared.u64 t,%1; cvt.u32.u64 %0,t;}" : "=r"(a) : "l"(p)); return a;
}
__device__ __forceinline__ uint32_t packh2(float x, float y) {
    __half2 hv = __floats2half2_rn(x, y);
    return *(uint32_t*)&hv;
}
#define LDM2(r0,r1,ad) asm volatile("ldmatrix.sync.aligned.m8n8.x2.shared.b16 {%0,%1},[%2];":"=r"(r0),"=r"(r1):"r"(ad))
#define MMA16(c,a0,a1,a2,a3,b0,b1) asm volatile("mma.sync.aligned.m16n8k16.row.col.f32.f16.f16.f32 {%0,%1,%2,%3},{%4,%5,%6,%7},{%8,%9},{%0,%1,%2,%3};":"+f"(c[0]),"+f"(c[1]),"+f"(c[2]),"+f"(c[3]):"r"(a0),"r"(a1),"r"(a2),"r"(a3),"r"(b0),"r"(b1))
#define ADRB(u,S,r0,k0) ((u) + ((((r0)+(lane&7))*(S) + (k0) + (((lane>>3)&1)<<3))<<1))

__global__ __launch_bounds__(THREADS, 2)
void gc_kernel(const float* __restrict__ bias2, float* __restrict__ out) {
    extern __shared__ __half sh[];
    __half* sXt = sh;              // [FF][NJ]
    __half* sKt = sXt + FF*NJ;     // [MR][SF]
    __half* sFH = sKt + MR*SF;     // [FF][SF]
    __half* sFL = sFH + FF*SF;

    const int bx = blockIdx.x, z = bx & 1, h = (bx >> 1) & 3, b = bx >> 3;
    const int tid = threadIdx.x, lane = tid & 31, w = tid >> 5;
    const int g = lane >> 2, t = lane & 3;

    {   // stage block-wide fp16 operands (16B copies)
        const uint4* s1 = (const uint4*)(g_XT + (size_t)b*FF*NJ); uint4* d1 = (uint4*)sXt;
        for (int i = tid; i < FF*NJ/8; i += THREADS) d1[i] = s1[i];
        const uint4* s2 = (const uint4*)(g_KT + (size_t)h*MR*SF); uint4* d2 = (uint4*)sKt;
        for (int i = tid; i < MR*SF/8; i += THREADS) d2[i] = s2[i];
        const uint4* s3 = (const uint4*)(g_FCC + (size_t)(h*2)*FF*SF); uint4* d3 = (uint4*)sFH;
        for (int i = tid; i < 2*FF*SF/8; i += THREADS) d3[i] = s3[i];
    }
    __syncthreads();

    const uint32_t uXt = s2u(sXt), uKt = s2u(sKt), uFH = s2u(sFH), uFL = s2u(sFL);
    const int m0 = (z*NWB + w)*16;
    const int mA = m0 + g, mB = m0 + g + 8;

    // ---- phase 1: feat = AWT x Xt^T (A frags from global, C stays in regs) ----
    uint32_t aF[4][4];
    {
        float c[8][4] = {};
        const __half* aw = g_AWT + ((size_t)h*MR + m0)*NJ;
        #pragma unroll
        for (int ks = 0; ks < 13; ks++) {
            const __half* pk = aw + 16*ks + 2*t;
            uint32_t a0 = *(const uint32_t*)(pk + g*NJ);
            uint32_t a1 = *(const uint32_t*)(pk + (g+8)*NJ);
            uint32_t a2 = *(const uint32_t*)(pk + g*NJ + 8);
            uint32_t a3 = *(const uint32_t*)(pk + (g+8)*NJ + 8);
            #pragma unroll
            for (int nt = 0; nt < 8; nt++) {
                uint32_t b0, b1; LDM2(b0, b1, ADRB(uXt, NJ, 8*nt, 16*ks));
                MMA16(c[nt], a0, a1, a2, a3, b0, b1);
            }
        }
        #pragma unroll
        for (int ks = 0; ks < 4; ks++) {    // C frag -> A frag of phase 2 (k = f axis)
            aF[ks][0] = packh2(c[2*ks][0],   c[2*ks][1]);
            aF[ks][1] = packh2(c[2*ks][2],   c[2*ks][3]);
            aF[ks][2] = packh2(c[2*ks+1][0], c[2*ks+1][1]);
            aF[ks][3] = packh2(c[2*ks+1][2], c[2*ks+1][3]);
        }
    }

    // ---- phase 2: dense = feat x Kt^T; accumulators pre-loaded with bias1/-inf ----
    float d[NT2][4];
    {
        const __half* md = g_MAD + ((size_t)h*MR + m0)*NJ + 2*t;
        #pragma unroll
        for (int nt = 0; nt < NT2; nt++) {
            __half2 u0 = *(const __half2*)(md + g*NJ + 8*nt);
            __half2 u1 = *(const __half2*)(md + (g+8)*NJ + 8*nt);
            float2 f0 = __half22float2(u0), f1 = __half22float2(u1);
            d[nt][0] = f0.x; d[nt][1] = f0.y; d[nt][2] = f1.x; d[nt][3] = f1.y;
        }
        #pragma unroll
        for (int ks = 0; ks < 4; ks++) {
            #pragma unroll
            for (int nt = 0; nt < NT2; nt++) {
                uint32_t b0, b1; LDM2(b0, b1, ADRB(uKt, SF, 8*nt, 16*ks));
                MMA16(d[nt], aF[ks][0], aF[ks][1], aF[ks][2], aF[ks][3], b0, b1);
            }
        }
    }

    // ---- softmax on frags; normalized mask packed directly into A frags ----
    uint32_t aM[13][4];
    {
        float mxA = -3e38f, mxB = -3e38f;
        #pragma unroll
        for (int nt = 0; nt < NT2; nt++) {
            mxA = fmaxf(mxA, fmaxf(d[nt][0], d[nt][1]));
            mxB = fmaxf(mxB, fmaxf(d[nt][2], d[nt][3]));
        }
        mxA = fmaxf(mxA, __shfl_xor_sync(~0u, mxA, 1)); mxA = fmaxf(mxA, __shfl_xor_sync(~0u, mxA, 2));
        mxB = fmaxf(mxB, __shfl_xor_sync(~0u, mxB, 1)); mxB = fmaxf(mxB, __shfl_xor_sync(~0u, mxB, 2));
        float sA = 0.f, sB = 0.f;
        #pragma unroll
        for (int nt = 0; nt < NT2; nt++) {
            d[nt][0] = __expf(d[nt][0] - mxA); d[nt][1] = __expf(d[nt][1] - mxA);
            d[nt][2] = __expf(d[nt][2] - mxB); d[nt][3] = __expf(d[nt][3] - mxB);
            sA += d[nt][0] + d[nt][1]; sB += d[nt][2] + d[nt][3];
        }
        sA += __shfl_xor_sync(~0u, sA, 1); sA += __shfl_xor_sync(~0u, sA, 2);
        sB += __shfl_xor_sync(~0u, sB, 1); sB += __shfl_xor_sync(~0u, sB, 2);
        float iA = 1.f/sA, iB = 1.f/sB;
        const bool wm = (h == 3);
        size_t oA = ((size_t)b*NN + mA)*OUTC + 256, oB = ((size_t)b*NN + mB)*OUTC + 256;
        #pragma unroll
        for (int nt = 0; nt < NT2; nt++) {
            float v0 = d[nt][0]*iA, v1 = d[nt][1]*iA, v2 = d[nt][2]*iB, v3 = d[nt][3]*iB;
            aM[nt>>1][(nt&1)*2 + 0] = packh2(v0, v1);
            aM[nt>>1][(nt&1)*2 + 1] = packh2(v2, v3);
            if (wm) {
                int j = 8*nt + 2*t;
                if (mA < NN) { if (j < NN) out[oA+j] = v0; if (j+1 < NN) out[oA+j+1] = v1; }
                if (mB < NN) { if (j < NN) out[oB+j] = v2; if (j+1 < NN) out[oB+j+1] = v3; }
            }
        }
        aM[12][2] = 0u; aM[12][3] = 0u;   // j=200..207 (dropped tile) is zero mask
    }

    // ---- phase 4: node = mask x Xt^T (A frags direct from registers) ----
    uint32_t aH[4][4], aL[4][4];
    {
        float c[8][4] = {};
        #pragma unroll
        for (int ks = 0; ks < 13; ks++) {
            #pragma unroll
            for (int nt = 0; nt < 8; nt++) {
                uint32_t b0, b1; LDM2(b0, b1, ADRB(uXt, NJ, 8*nt, 16*ks));
                MMA16(c[nt], aM[ks][0], aM[ks][1], aM[ks][2], aM[ks][3], b0, b1);
            }
        }
        #pragma unroll
        for (int ks = 0; ks < 4; ks++) {    // node hi/lo split, packed as phase-5 A frags
            #pragma unroll
            for (int q = 0; q < 4; q++) {
                int nt = 2*ks + (q >> 1);
                float x = c[nt][(q&1)*2], y = c[nt][(q&1)*2+1];
                __half hx = __float2half_rn(x), hy = __float2half_rn(y);
                __half2 hv = __halves2half2(hx, hy);
                aH[ks][q] = *(uint32_t*)&hv;
                __half2 lv = __floats2half2_rn(x - __half2float(hx), y - __half2float(hy));
                aL[ks][q] = *(uint32_t*)&lv;
            }
        }
    }

    // ---- phase 5: out = nodeH*fcH + nodeL*fcH + nodeH*fcL + bias2 ----
    {
        float c[8][4] = {};
        #pragma unroll
        for (int ks = 0; ks < 4; ks++) {
            #pragma unroll
            for (int nt = 0; nt < 8; nt++) {
                uint32_t bH0, bH1, bL0, bL1;
                LDM2(bH0, bH1, ADRB(uFH, SF, 8*nt, 16*ks));
                LDM2(bL0, bL1, ADRB(uFL, SF, 8*nt, 16*ks));
                MMA16(c[nt], aH[ks][0], aH[ks][1], aH[ks][2], aH[ks][3], bH0, bH1);
                MMA16(c[nt], aL[ks][0], aL[ks][1], aL[ks][2], aL[ks][3], bH0, bH1);
                MMA16(c[nt], aH[ks][0], aH[ks][1], aH[ks][2], aH[ks][3], bL0, bL1);
            }
        }
        size_t oA = ((size_t)b*NN + mA)*OUTC + h*64, oB = ((size_t)b*NN + mB)*OUTC + h*64;
        #pragma unroll
        for (int nt = 0; nt < 8; nt++) {
            int u = 8*nt + 2*t;
            float2 b2 = *(const float2*)&bias2[h*64 + u];
            if (mA < NN) {                 // OUTC odd: scalar stores
                out[oA+u]   = c[nt][0] + b2.x;
                out[oA+u+1] = c[nt][1] + b2.y;
            }
            if (mB < NN) {
                out[oB+u]   = c[nt][2] + b2.x;
                out[oB+u+1] = c[nt][3] + b2.y;
            }
        }
    }
}

extern "C" void kernel_launch(void* const* d_in, const int* in_sizes, int n_in,
                              void* d_out, int out_size)
{
    const float* X  = (const float*)d_in[0];
    const float* A  = (const float*)d_in[1];
    const float* Kn = (const float*)d_in[2];
    const float* P  = (const float*)d_in[3];
    const float* FC = (const float*)d_in[4];
    const float* B1 = (const float*)d_in[5];
    const float* B2 = (const float*)d_in[6];
    float* out = (float*)d_out;

    int B = in_sizes[0] / (NN*FF);

    int tot = HH*MR*NJ + HH*MR*SF + HH*2*FF*SF;
    prep_const<<<(tot + 255)/256, 256>>>(A, P, Kn, FC, B1);
    prep_x<<<B, 256>>>(X);

    const int smemBytes = (FF*NJ + MR*SF + 2*FF*SF) * 2;   // 78,336 B
    cudaFuncSetAttribute(gc_kernel, cudaFuncAttributeMaxDynamicSharedMemorySize, smemBytes);
    gc_kernel<<<B*HH*2, THREADS, smemBytes>>>(B2, out);
}